// round 6
// baseline (speedup 1.0000x reference)
#include <cuda_runtime.h>
#include <cstddef>

#define B_SZ 8
#define T_SZ 2048
#define C_SZ 1024
#define H_SZ 64
#define MROWS (B_SZ * T_SZ)

typedef unsigned long long u64;

__device__ __forceinline__ u64 pack_dup(float x) {
    u64 r; asm("mov.b64 %0, {%1, %1};" : "=l"(r) : "f"(x)); return r;
}
__device__ __forceinline__ void fma2(u64& c, u64 a, u64 b) {
    asm("fma.rn.f32x2 %0, %1, %2, %0;" : "+l"(c) : "l"(a), "l"(b));
}
__device__ __forceinline__ void mul2(u64& c, u64 a) {
    asm("mul.rn.f32x2 %0, %0, %1;" : "+l"(c) : "l"(a));
}
__device__ __forceinline__ float2 unpack2(u64 v) {
    float2 f; asm("mov.b64 {%0, %1}, %2;" : "=f"(f.x), "=f"(f.y) : "l"(v)); return f;
}

// Scratch for q, k, v projections (4 MB each).
__device__ float g_q[MROWS * H_SZ];
__device__ float g_k[MROWS * H_SZ];
__device__ float g_v[MROWS * H_SZ];

// ---------------------------------------------------------------------------
// Kernel 1: FUSED QKV projections.  q/k/v = x @ {Wq,Wk,Wv}
// Tile: 64 (M) x 64 (N) x 16 (K).  256 threads, micro 2x8 per W.
// x tile read ONCE for all three outputs; double-buffered via reg prefetch.
// ---------------------------------------------------------------------------
__global__ __launch_bounds__(256) void qkv_kernel(
    const float* __restrict__ x,
    const float* __restrict__ Wq,
    const float* __restrict__ Wk,
    const float* __restrict__ Wv)
{
    __shared__ __align__(16) float xs[2][16][132];   // [buf][k][m] transposed
    __shared__ __align__(16) float ws[2][3][16][64]; // [buf][w][k][n]

    const int m0 = blockIdx.x * 64;
    const int t  = threadIdx.x;
    const int ty = t >> 3;          // 0..31 -> rows ty*2, ty*2+1
    const int tx = t & 7;           // cols tx*8 .. +8
    const int xr   = t >> 2;        // x load row 0..63
    const int xseg = (t & 3) * 4;   // x load col segment
    const int wkr  = t >> 4;        // W load k-row 0..15
    const int wnc  = (t & 15) * 4;  // W load n-col

    u64 acc[3][2][4];
#pragma unroll
    for (int w = 0; w < 3; w++)
#pragma unroll
        for (int i = 0; i < 2; i++)
#pragma unroll
            for (int j = 0; j < 4; j++) acc[w][i][j] = 0ULL;

    const float* xrow = x + (size_t)(m0 + xr) * C_SZ + xseg;

    // Prologue prefetch (k0 = 0)
    float4 xa  = *(const float4*)(xrow);
    float4 wr0 = *(const float4*)(Wq + (size_t)wkr * H_SZ + wnc);
    float4 wr1 = *(const float4*)(Wk + (size_t)wkr * H_SZ + wnc);
    float4 wr2 = *(const float4*)(Wv + (size_t)wkr * H_SZ + wnc);

    for (int k0 = 0; k0 < C_SZ; k0 += 16) {
        const int cur = (k0 >> 4) & 1;
        // Store prefetched tile
        xs[cur][xseg + 0][xr] = xa.x;
        xs[cur][xseg + 1][xr] = xa.y;
        xs[cur][xseg + 2][xr] = xa.z;
        xs[cur][xseg + 3][xr] = xa.w;
        *(float4*)&ws[cur][0][wkr][wnc] = wr0;
        *(float4*)&ws[cur][1][wkr][wnc] = wr1;
        *(float4*)&ws[cur][2][wkr][wnc] = wr2;
        __syncthreads();

        // Prefetch next tile (overlaps with compute below)
        if (k0 + 16 < C_SZ) {
            xa  = *(const float4*)(xrow + k0 + 16);
            wr0 = *(const float4*)(Wq + (size_t)(k0 + 16 + wkr) * H_SZ + wnc);
            wr1 = *(const float4*)(Wk + (size_t)(k0 + 16 + wkr) * H_SZ + wnc);
            wr2 = *(const float4*)(Wv + (size_t)(k0 + 16 + wkr) * H_SZ + wnc);
        }

#pragma unroll
        for (int kk = 0; kk < 16; kk++) {
            float2 a = *(const float2*)&xs[cur][kk][ty * 2];
            u64 a0 = pack_dup(a.x), a1 = pack_dup(a.y);
#pragma unroll
            for (int w = 0; w < 3; w++) {
                ulonglong2 b01 = *(const ulonglong2*)&ws[cur][w][kk][tx * 8];
                ulonglong2 b23 = *(const ulonglong2*)&ws[cur][w][kk][tx * 8 + 4];
                fma2(acc[w][0][0], a0, b01.x); fma2(acc[w][0][1], a0, b01.y);
                fma2(acc[w][0][2], a0, b23.x); fma2(acc[w][0][3], a0, b23.y);
                fma2(acc[w][1][0], a1, b01.x); fma2(acc[w][1][1], a1, b01.y);
                fma2(acc[w][1][2], a1, b23.x); fma2(acc[w][1][3], a1, b23.y);
            }
        }
        __syncthreads();
    }

    float* outs[3] = {g_q, g_k, g_v};
#pragma unroll
    for (int w = 0; w < 3; w++)
#pragma unroll
        for (int i = 0; i < 2; i++) {
            float2 p0 = unpack2(acc[w][i][0]);
            float2 p1 = unpack2(acc[w][i][1]);
            float2 p2 = unpack2(acc[w][i][2]);
            float2 p3 = unpack2(acc[w][i][3]);
            float* orow = outs[w] + (size_t)(m0 + ty * 2 + i) * H_SZ + tx * 8;
            *(float4*)orow       = make_float4(p0.x, p0.y, p1.x, p1.y);
            *(float4*)(orow + 4) = make_float4(p2.x, p2.y, p3.x, p3.y);
        }
}

// ---------------------------------------------------------------------------
// Kernel 2: causal attention.  512 threads, 64q x 64k tiles, micro 2x4.
// Paired q-tiles (qb, 31-qb), double-buffered K/V via register prefetch.
// ---------------------------------------------------------------------------
#define QST 68
#define SM_K_OFF (64 * QST)
#define SM_P_OFF (SM_K_OFF + 2 * 64 * QST)
#define SM_V_OFF (SM_P_OFF + 64 * QST)
#define SM_S_OFF (SM_V_OFF + 2 * 64 * 64)
#define ATTN_SMEM_BYTES ((SM_S_OFF + 3 * 64) * 4)

__global__ __launch_bounds__(512) void attn_kernel(float* __restrict__ out)
{
    extern __shared__ __align__(16) float sm[];
    float* smQ = sm;                 // [64h][QST]  Q^T
    float* smP = sm + SM_P_OFF;      // [64i][QST]  P row-major
    float* s_m = sm + SM_S_OFF;
    float* s_l = s_m + 64;
    float* s_a = s_l + 64;

    const int b  = blockIdx.y;
    const int t  = threadIdx.x;
    const int tx = t & 15;          // cols tx*4
    const int ty = t >> 4;          // 0..31 -> rows ty*2, ty*2+1
    const int lr = t >> 3;          // load row 0..63
    const int lc = (t & 7) * 8;     // load col segment
    const int srow  = t >> 3;       // softmax row
    const int spart = t & 7;        // softmax partition (8/row)

    const float* qp = g_q + (size_t)b * T_SZ * H_SZ;
    const float* kp = g_k + (size_t)b * T_SZ * H_SZ;
    const float* vp = g_v + (size_t)b * T_SZ * H_SZ;

    for (int pass = 0; pass < 2; pass++) {
        const int qb = pass ? 31 - (int)blockIdx.x : (int)blockIdx.x;
        const int q0 = qb * 64;

        __syncthreads();   // protect smem/s_l from previous pass

        // Load Q tile transposed
        {
            const float* qr = qp + (size_t)(q0 + lr) * H_SZ + lc;
            float4 qv0 = *(const float4*)qr;
            float4 qv1 = *(const float4*)(qr + 4);
            smQ[(lc + 0) * QST + lr] = qv0.x; smQ[(lc + 1) * QST + lr] = qv0.y;
            smQ[(lc + 2) * QST + lr] = qv0.z; smQ[(lc + 3) * QST + lr] = qv0.w;
            smQ[(lc + 4) * QST + lr] = qv1.x; smQ[(lc + 5) * QST + lr] = qv1.y;
            smQ[(lc + 6) * QST + lr] = qv1.z; smQ[(lc + 7) * QST + lr] = qv1.w;
        }
        if (t < 64) { s_m[t] = -1e30f; s_l[t] = 0.0f; }

        u64 acc[2][2];
        acc[0][0] = acc[0][1] = acc[1][0] = acc[1][1] = 0ULL;

        // Prefetch KV tile 0
        float4 kf0, kf1, vf0, vf1;
        {
            const float* kr = kp + (size_t)lr * H_SZ + lc;
            kf0 = *(const float4*)kr; kf1 = *(const float4*)(kr + 4);
            const float* vr = vp + (size_t)lr * H_SZ + lc;
            vf0 = *(const float4*)vr; vf1 = *(const float4*)(vr + 4);
        }
        __syncthreads();

        for (int kb = 0; kb <= qb; kb++) {
            const int cur = kb & 1;
            float* kbuf = sm + SM_K_OFF + cur * 64 * QST;   // K^T [h][n]
            float* vbuf = sm + SM_V_OFF + cur * 64 * 64;    // V   [j][v]

            // Store prefetched K (transposed) and V
            kbuf[(lc + 0) * QST + lr] = kf0.x; kbuf[(lc + 1) * QST + lr] = kf0.y;
            kbuf[(lc + 2) * QST + lr] = kf0.z; kbuf[(lc + 3) * QST + lr] = kf0.w;
            kbuf[(lc + 4) * QST + lr] = kf1.x; kbuf[(lc + 5) * QST + lr] = kf1.y;
            kbuf[(lc + 6) * QST + lr] = kf1.z; kbuf[(lc + 7) * QST + lr] = kf1.w;
            *(float4*)&vbuf[lr * 64 + lc]     = vf0;
            *(float4*)&vbuf[lr * 64 + lc + 4] = vf1;
            __syncthreads();

            // Prefetch next KV tile (overlaps QK + softmax + PV)
            if (kb < qb) {
                const float* kr = kp + (size_t)((kb + 1) * 64 + lr) * H_SZ + lc;
                kf0 = *(const float4*)kr; kf1 = *(const float4*)(kr + 4);
                const float* vr = vp + (size_t)((kb + 1) * 64 + lr) * H_SZ + lc;
                vf0 = *(const float4*)vr; vf1 = *(const float4*)(vr + 4);
            }

            // S = Q K^T
            u64 s2[2][2];
            s2[0][0] = s2[0][1] = s2[1][0] = s2[1][1] = 0ULL;
#pragma unroll 16
            for (int h = 0; h < 64; h++) {
                float2 a = *(const float2*)&smQ[h * QST + ty * 2];
                ulonglong2 bb = *(const ulonglong2*)&kbuf[h * QST + tx * 4];
                u64 a0 = pack_dup(a.x), a1 = pack_dup(a.y);
                fma2(s2[0][0], a0, bb.x); fma2(s2[0][1], a0, bb.y);
                fma2(s2[1][0], a1, bb.x); fma2(s2[1][1], a1, bb.y);
            }

            const bool diag = (kb == qb);
#pragma unroll
            for (int i = 0; i < 2; i++) {
                const int row = ty * 2 + i;
                float2 lo = unpack2(s2[i][0]);
                float2 hi = unpack2(s2[i][1]);
                float4 v = make_float4(lo.x * 0.03125f, lo.y * 0.03125f,
                                       hi.x * 0.03125f, hi.y * 0.03125f);
                if (diag) {
                    if (tx * 4 + 0 > row) v.x = -1e30f;
                    if (tx * 4 + 1 > row) v.y = -1e30f;
                    if (tx * 4 + 2 > row) v.z = -1e30f;
                    if (tx * 4 + 3 > row) v.w = -1e30f;
                }
                *(float4*)&smP[row * QST + tx * 4] = v;
            }
            __syncthreads();

            // Online softmax: 8 threads per row
            {
                float4 p0 = *(const float4*)&smP[srow * QST + spart * 8];
                float4 p1 = *(const float4*)&smP[srow * QST + spart * 8 + 4];
                float lmx = fmaxf(fmaxf(fmaxf(p0.x, p0.y), fmaxf(p0.z, p0.w)),
                                  fmaxf(fmaxf(p1.x, p1.y), fmaxf(p1.z, p1.w)));
                lmx = fmaxf(lmx, __shfl_xor_sync(0xffffffffu, lmx, 1));
                lmx = fmaxf(lmx, __shfl_xor_sync(0xffffffffu, lmx, 2));
                lmx = fmaxf(lmx, __shfl_xor_sync(0xffffffffu, lmx, 4));
                float m_old = s_m[srow];
                float mx = fmaxf(m_old, lmx);
                p0.x = __expf(p0.x - mx); p0.y = __expf(p0.y - mx);
                p0.z = __expf(p0.z - mx); p0.w = __expf(p0.w - mx);
                p1.x = __expf(p1.x - mx); p1.y = __expf(p1.y - mx);
                p1.z = __expf(p1.z - mx); p1.w = __expf(p1.w - mx);
                *(float4*)&smP[srow * QST + spart * 8]     = p0;
                *(float4*)&smP[srow * QST + spart * 8 + 4] = p1;
                float ls = (p0.x + p0.y) + (p0.z + p0.w)
                         + (p1.x + p1.y) + (p1.z + p1.w);
                ls += __shfl_xor_sync(0xffffffffu, ls, 1);
                ls += __shfl_xor_sync(0xffffffffu, ls, 2);
                ls += __shfl_xor_sync(0xffffffffu, ls, 4);
                if (spart == 0) {
                    float alpha = __expf(m_old - mx);
                    s_a[srow] = alpha;
                    s_l[srow] = s_l[srow] * alpha + ls;
                    s_m[srow] = mx;
                }
            }
            __syncthreads();

            // Rescale accumulators, then acc += P @ V
            {
                u64 al0 = pack_dup(s_a[ty * 2]);
                u64 al1 = pack_dup(s_a[ty * 2 + 1]);
                mul2(acc[0][0], al0); mul2(acc[0][1], al0);
                mul2(acc[1][0], al1); mul2(acc[1][1], al1);
            }
#pragma unroll 8
            for (int j = 0; j < 64; j += 2) {
                float2 pr0 = *(const float2*)&smP[(ty * 2) * QST + j];
                float2 pr1 = *(const float2*)&smP[(ty * 2 + 1) * QST + j];
                ulonglong2 v0 = *(const ulonglong2*)&vbuf[j * 64 + tx * 4];
                ulonglong2 v1 = *(const ulonglong2*)&vbuf[(j + 1) * 64 + tx * 4];
                u64 p00 = pack_dup(pr0.x), p01 = pack_dup(pr0.y);
                u64 p10 = pack_dup(pr1.x), p11 = pack_dup(pr1.y);
                fma2(acc[0][0], p00, v0.x); fma2(acc[0][1], p00, v0.y);
                fma2(acc[1][0], p10, v0.x); fma2(acc[1][1], p10, v0.y);
                fma2(acc[0][0], p01, v1.x); fma2(acc[0][1], p01, v1.y);
                fma2(acc[1][0], p11, v1.x); fma2(acc[1][1], p11, v1.y);
            }
            // No trailing sync needed: next iteration's top sync (after the
            // opposite-buffer store) orders all readers before any rewrite.
        }

        // Normalize and write out
#pragma unroll
        for (int i = 0; i < 2; i++) {
            const int row = ty * 2 + i;
            float inv = 1.0f / s_l[row];
            float2 o01 = unpack2(acc[i][0]);
            float2 o23 = unpack2(acc[i][1]);
            float4 o = make_float4(o01.x * inv, o01.y * inv,
                                   o23.x * inv, o23.y * inv);
            *(float4*)(out + (size_t)(b * T_SZ + q0 + row) * H_SZ + tx * 4) = o;
        }
    }
}

// ---------------------------------------------------------------------------
extern "C" void kernel_launch(void* const* d_in, const int* in_sizes, int n_in,
                              void* d_out, int out_size)
{
    const float* x  = (const float*)d_in[0];
    const float* Wq = (const float*)d_in[1];
    const float* Wk = (const float*)d_in[2];
    const float* Wv = (const float*)d_in[3];
    float* out = (float*)d_out;

    cudaFuncSetAttribute(attn_kernel, cudaFuncAttributeMaxDynamicSharedMemorySize,
                         ATTN_SMEM_BYTES);

    qkv_kernel<<<dim3(MROWS / 64), 256>>>(x, Wq, Wk, Wv);
    attn_kernel<<<dim3(16, B_SZ), 512, ATTN_SMEM_BYTES>>>(out);
}

// round 8
// speedup vs baseline: 2.2261x; 2.2261x over previous
#include <cuda_runtime.h>
#include <cuda_bf16.h>
#include <cstdint>
#include <cstddef>

#define B_SZ 8
#define T_SZ 2048
#define C_SZ 1024
#define H_SZ 64
#define MROWS (B_SZ * T_SZ)

typedef unsigned long long u64;

// ---------------- scalar f32x2 helpers (attention) ----------------
__device__ __forceinline__ u64 pack_dup(float x) {
    u64 r; asm("mov.b64 %0, {%1, %1};" : "=l"(r) : "f"(x)); return r;
}
__device__ __forceinline__ void fma2(u64& c, u64 a, u64 b) {
    asm("fma.rn.f32x2 %0, %1, %2, %0;" : "+l"(c) : "l"(a), "l"(b));
}
__device__ __forceinline__ void mul2(u64& c, u64 a) {
    asm("mul.rn.f32x2 %0, %0, %1;" : "+l"(c) : "l"(a));
}
__device__ __forceinline__ float2 unpack2(u64 v) {
    float2 f; asm("mov.b64 {%0, %1}, %2;" : "=f"(f.x), "=f"(f.y) : "l"(v)); return f;
}

// ---------------- mma.sync helpers ----------------
__device__ __forceinline__ uint32_t smem_u32(const void* p) {
    uint32_t a;
    asm("{ .reg .u64 t; cvta.to.shared.u64 t, %1; cvt.u32.u64 %0, t; }" : "=r"(a) : "l"(p));
    return a;
}
__device__ __forceinline__ void ldsm_x4(uint32_t& r0, uint32_t& r1,
                                        uint32_t& r2, uint32_t& r3, uint32_t addr) {
    asm volatile("ldmatrix.sync.aligned.m8n8.x4.shared.b16 {%0,%1,%2,%3}, [%4];"
                 : "=r"(r0), "=r"(r1), "=r"(r2), "=r"(r3) : "r"(addr));
}
__device__ __forceinline__ void mma_bf16(float* c, const uint32_t* a,
                                         uint32_t b0, uint32_t b1) {
    asm volatile(
        "mma.sync.aligned.m16n8k16.row.col.f32.bf16.bf16.f32 "
        "{%0,%1,%2,%3}, {%4,%5,%6,%7}, {%8,%9}, {%0,%1,%2,%3};"
        : "+f"(c[0]), "+f"(c[1]), "+f"(c[2]), "+f"(c[3])
        : "r"(a[0]), "r"(a[1]), "r"(a[2]), "r"(a[3]), "r"(b0), "r"(b1));
}

// ---------------- scratch ----------------
__device__ float g_q[MROWS * H_SZ];
__device__ float g_k[MROWS * H_SZ];
__device__ float g_v[MROWS * H_SZ];
__device__ __nv_bfloat16 g_wT_hi[3][64][C_SZ];   // [w][n][k]
__device__ __nv_bfloat16 g_wT_lo[3][64][C_SZ];

// ---------------------------------------------------------------------------
// Kernel 0: transpose + bf16 hi/lo split of the three weight matrices.
// ---------------------------------------------------------------------------
__global__ __launch_bounds__(256) void wsplit_kernel(
    const float* __restrict__ Wq, const float* __restrict__ Wk,
    const float* __restrict__ Wv)
{
    __shared__ float tile[64][65];
    const int w  = blockIdx.y;
    const int k0 = blockIdx.x * 64;
    const float* W = (w == 0) ? Wq : (w == 1) ? Wk : Wv;
    const int t = threadIdx.x;

    {
        int r = t >> 2, cs = (t & 3) * 16;
#pragma unroll
        for (int j = 0; j < 4; j++) {
            float4 v = *(const float4*)(W + (size_t)(k0 + r) * 64 + cs + j * 4);
            tile[r][cs + j * 4 + 0] = v.x; tile[r][cs + j * 4 + 1] = v.y;
            tile[r][cs + j * 4 + 2] = v.z; tile[r][cs + j * 4 + 3] = v.w;
        }
    }
    __syncthreads();
    {
        int n = t >> 2, ks = (t & 3) * 16;
        union { __nv_bfloat16 b[16]; uint4 u[2]; } H, L;
#pragma unroll
        for (int i = 0; i < 16; i++) {
            float v = tile[ks + i][n];
            __nv_bfloat16 h = __float2bfloat16(v);
            H.b[i] = h;
            L.b[i] = __float2bfloat16(v - __bfloat162float(h));
        }
        *(uint4*)&g_wT_hi[w][n][k0 + ks]     = H.u[0];
        *(uint4*)&g_wT_hi[w][n][k0 + ks + 8] = H.u[1];
        *(uint4*)&g_wT_lo[w][n][k0 + ks]     = L.u[0];
        *(uint4*)&g_wT_lo[w][n][k0 + ks + 8] = L.u[1];
    }
}

// ---------------------------------------------------------------------------
// Kernel 1: QKV projections via mma.sync bf16, split hi/lo 3-term.
// CTA: 512 threads (16 warps), M=128, N = 3x64, K chunked by 64.
// Warp (mw = wid&7, wsel = wid>>3): rows mw*16..+16, flat ncols wsel*12..+12
// (ncol 0..23 -> w = ncol/8, ntile = ncol%8).
// smem: A_hi/A_lo [128][72 bf16] (144B stride), B [6][64][72 bf16].
// ---------------------------------------------------------------------------
#define A_HI_OFF 0
#define A_LO_OFF 18432
#define B_OFF    36864
#define QKV_SMEM (B_OFF + 6 * 9216)

__global__ __launch_bounds__(512) void qkv_mma_kernel(const float* __restrict__ x)
{
    extern __shared__ __align__(128) char smem_raw[];
    const uint32_t sb = smem_u32(smem_raw);
    const int t = threadIdx.x;
    const int wid = t >> 5, L = t & 31;
    const int mw = wid & 7, wsel = wid >> 3;
    const int m0 = blockIdx.x * 128;

    // Per-lane ldmatrix base addresses
    const uint32_t aRow  = mw * 16 + (L & 15);
    const uint32_t aHiB  = sb + A_HI_OFF + aRow * 144 + (L >> 4) * 16;
    const uint32_t aLoB  = sb + A_LO_OFF + aRow * 144 + (L >> 4) * 16;
    const uint32_t bLane = sb + B_OFF + ((L & 7) + ((L >> 4) & 1) * 8) * 144
                         + ((L >> 3) & 1) * 16;

    // Conversion / copy indices
    const int ar   = t >> 2;            // x row 0..127
    const int aseg = (t & 3) * 16;      // 16 floats
    const float* xrow = x + (size_t)(m0 + ar) * C_SZ + aseg;

    const __nv_bfloat16* bsrc[6] = {
        &g_wT_hi[0][0][0], &g_wT_lo[0][0][0],
        &g_wT_hi[1][0][0], &g_wT_lo[1][0][0],
        &g_wT_hi[2][0][0], &g_wT_lo[2][0][0] };

    float acc[12][4];
#pragma unroll
    for (int i = 0; i < 12; i++)
#pragma unroll
        for (int j = 0; j < 4; j++) acc[i][j] = 0.0f;

    for (int kb = 0; kb < 16; kb++) {
        // ---- convert x block -> bf16 hi/lo into smem
#pragma unroll
        for (int c = 0; c < 2; c++) {
            float4 v0 = *(const float4*)(xrow + kb * 64 + c * 8);
            float4 v1 = *(const float4*)(xrow + kb * 64 + c * 8 + 4);
            float vv[8] = {v0.x, v0.y, v0.z, v0.w, v1.x, v1.y, v1.z, v1.w};
            union { __nv_bfloat16 b[8]; uint4 u; } H, Lo;
#pragma unroll
            for (int i = 0; i < 8; i++) {
                __nv_bfloat16 h = __float2bfloat16(vv[i]);
                H.b[i] = h;
                Lo.b[i] = __float2bfloat16(vv[i] - __bfloat162float(h));
            }
            const uint32_t off = ar * 144 + (aseg + c * 8) * 2;
            *(uint4*)(smem_raw + A_HI_OFF + off) = H.u;
            *(uint4*)(smem_raw + A_LO_OFF + off) = Lo.u;
        }
        // ---- copy pre-split W^T block (6 bufs x 64n x 64k bf16)
#pragma unroll
        for (int i = 0; i < 6; i++) {
            const int idx = t + i * 512;      // 0..3071
            const int buf = idx >> 9;
            const int rem = idx & 511;
            const int n = rem >> 3, kc = rem & 7;
            uint4 v = *(const uint4*)(bsrc[buf] + (size_t)n * C_SZ + kb * 64 + kc * 8);
            *(uint4*)(smem_raw + B_OFF + buf * 9216 + n * 144 + kc * 16) = v;
        }
        __syncthreads();

        // ---- MMA over this chunk: 4 k-steps of 16
#pragma unroll
        for (int ks = 0; ks < 4; ks++) {
            const uint32_t kbyte = ks * 32;
            uint32_t ah[4], al[4];
            ldsm_x4(ah[0], ah[1], ah[2], ah[3], aHiB + kbyte);
            ldsm_x4(al[0], al[1], al[2], al[3], aLoB + kbyte);
#pragma unroll
            for (int p = 0; p < 6; p++) {
                const int nc = wsel * 12 + 2 * p;
                const int w = nc >> 3, nt = nc & 7;
                const uint32_t bbase = bLane + (w * 2) * 9216 + nt * 1152 + kbyte;
                uint32_t bh[4], bl[4];
                ldsm_x4(bh[0], bh[1], bh[2], bh[3], bbase);
                ldsm_x4(bl[0], bl[1], bl[2], bl[3], bbase + 9216);
                // ncol nc (regs bh[0],bh[1] / bl[0],bl[1])
                mma_bf16(acc[2 * p],     ah, bh[0], bh[1]);
                mma_bf16(acc[2 * p],     al, bh[0], bh[1]);
                mma_bf16(acc[2 * p],     ah, bl[0], bl[1]);
                // ncol nc+1
                mma_bf16(acc[2 * p + 1], ah, bh[2], bh[3]);
                mma_bf16(acc[2 * p + 1], al, bh[2], bh[3]);
                mma_bf16(acc[2 * p + 1], ah, bl[2], bl[3]);
            }
        }
        __syncthreads();
    }

    // ---- epilogue: fp32 accumulators -> g_q/g_k/g_v
    float* outs[3] = {g_q, g_k, g_v};
    const int rrow = mw * 16 + (L >> 2);
    const int ccol = (L & 3) * 2;
#pragma unroll
    for (int ln = 0; ln < 12; ln++) {
        const int nc = wsel * 12 + ln;
        const int w = nc >> 3, nt = nc & 7;
        float* obase = outs[w] + (size_t)(m0 + rrow) * H_SZ + nt * 8 + ccol;
        *(float2*)obase                 = make_float2(acc[ln][0], acc[ln][1]);
        *(float2*)(obase + 8 * H_SZ)    = make_float2(acc[ln][2], acc[ln][3]);
    }
}

// ---------------------------------------------------------------------------
// Kernel 2: causal attention (scalar f32x2 — unchanged from best version).
// ---------------------------------------------------------------------------
#define QST 68
#define SM_K_OFF (64 * QST)
#define SM_P_OFF (SM_K_OFF + 2 * 64 * QST)
#define SM_V_OFF (SM_P_OFF + 64 * QST)
#define SM_S_OFF (SM_V_OFF + 2 * 64 * 64)
#define ATTN_SMEM_BYTES ((SM_S_OFF + 3 * 64) * 4)

__global__ __launch_bounds__(512) void attn_kernel(float* __restrict__ out)
{
    extern __shared__ __align__(128) char smem_raw[];
    float* sm = (float*)smem_raw;
    float* smQ = sm;
    float* smP = sm + SM_P_OFF;
    float* s_m = sm + SM_S_OFF;
    float* s_l = s_m + 64;
    float* s_a = s_l + 64;

    const int b  = blockIdx.y;
    const int t  = threadIdx.x;
    const int tx = t & 15;
    const int ty = t >> 4;
    const int lr = t >> 3;
    const int lc = (t & 7) * 8;
    const int srow  = t >> 3;
    const int spart = t & 7;

    const float* qp = g_q + (size_t)b * T_SZ * H_SZ;
    const float* kp = g_k + (size_t)b * T_SZ * H_SZ;
    const float* vp = g_v + (size_t)b * T_SZ * H_SZ;

    for (int pass = 0; pass < 2; pass++) {
        const int qb = pass ? 31 - (int)blockIdx.x : (int)blockIdx.x;
        const int q0 = qb * 64;

        __syncthreads();

        {
            const float* qr = qp + (size_t)(q0 + lr) * H_SZ + lc;
            float4 qv0 = *(const float4*)qr;
            float4 qv1 = *(const float4*)(qr + 4);
            smQ[(lc + 0) * QST + lr] = qv0.x; smQ[(lc + 1) * QST + lr] = qv0.y;
            smQ[(lc + 2) * QST + lr] = qv0.z; smQ[(lc + 3) * QST + lr] = qv0.w;
            smQ[(lc + 4) * QST + lr] = qv1.x; smQ[(lc + 5) * QST + lr] = qv1.y;
            smQ[(lc + 6) * QST + lr] = qv1.z; smQ[(lc + 7) * QST + lr] = qv1.w;
        }
        if (t < 64) { s_m[t] = -1e30f; s_l[t] = 0.0f; }

        u64 acc[2][2];
        acc[0][0] = acc[0][1] = acc[1][0] = acc[1][1] = 0ULL;

        float4 kf0, kf1, vf0, vf1;
        {
            const float* kr = kp + (size_t)lr * H_SZ + lc;
            kf0 = *(const float4*)kr; kf1 = *(const float4*)(kr + 4);
            const float* vr = vp + (size_t)lr * H_SZ + lc;
            vf0 = *(const float4*)vr; vf1 = *(const float4*)(vr + 4);
        }
        __syncthreads();

        for (int kb = 0; kb <= qb; kb++) {
            const int cur = kb & 1;
            float* kbuf = sm + SM_K_OFF + cur * 64 * QST;
            float* vbuf = sm + SM_V_OFF + cur * 64 * 64;

            kbuf[(lc + 0) * QST + lr] = kf0.x; kbuf[(lc + 1) * QST + lr] = kf0.y;
            kbuf[(lc + 2) * QST + lr] = kf0.z; kbuf[(lc + 3) * QST + lr] = kf0.w;
            kbuf[(lc + 4) * QST + lr] = kf1.x; kbuf[(lc + 5) * QST + lr] = kf1.y;
            kbuf[(lc + 6) * QST + lr] = kf1.z; kbuf[(lc + 7) * QST + lr] = kf1.w;
            *(float4*)&vbuf[lr * 64 + lc]     = vf0;
            *(float4*)&vbuf[lr * 64 + lc + 4] = vf1;
            __syncthreads();

            if (kb < qb) {
                const float* kr = kp + (size_t)((kb + 1) * 64 + lr) * H_SZ + lc;
                kf0 = *(const float4*)kr; kf1 = *(const float4*)(kr + 4);
                const float* vr = vp + (size_t)((kb + 1) * 64 + lr) * H_SZ + lc;
                vf0 = *(const float4*)vr; vf1 = *(const float4*)(vr + 4);
            }

            u64 s2[2][2];
            s2[0][0] = s2[0][1] = s2[1][0] = s2[1][1] = 0ULL;
#pragma unroll 16
            for (int h = 0; h < 64; h++) {
                float2 a = *(const float2*)&smQ[h * QST + ty * 2];
                ulonglong2 bb = *(const ulonglong2*)&kbuf[h * QST + tx * 4];
                u64 a0 = pack_dup(a.x), a1 = pack_dup(a.y);
                fma2(s2[0][0], a0, bb.x); fma2(s2[0][1], a0, bb.y);
                fma2(s2[1][0], a1, bb.x); fma2(s2[1][1], a1, bb.y);
            }

            const bool diag = (kb == qb);
#pragma unroll
            for (int i = 0; i < 2; i++) {
                const int row = ty * 2 + i;
                float2 lo = unpack2(s2[i][0]);
                float2 hi = unpack2(s2[i][1]);
                float4 v = make_float4(lo.x * 0.03125f, lo.y * 0.03125f,
                                       hi.x * 0.03125f, hi.y * 0.03125f);
                if (diag) {
                    if (tx * 4 + 0 > row) v.x = -1e30f;
                    if (tx * 4 + 1 > row) v.y = -1e30f;
                    if (tx * 4 + 2 > row) v.z = -1e30f;
                    if (tx * 4 + 3 > row) v.w = -1e30f;
                }
                *(float4*)&smP[row * QST + tx * 4] = v;
            }
            __syncthreads();

            {
                float4 p0 = *(const float4*)&smP[srow * QST + spart * 8];
                float4 p1 = *(const float4*)&smP[srow * QST + spart * 8 + 4];
                float lmx = fmaxf(fmaxf(fmaxf(p0.x, p0.y), fmaxf(p0.z, p0.w)),
                                  fmaxf(fmaxf(p1.x, p1.y), fmaxf(p1.z, p1.w)));
                lmx = fmaxf(lmx, __shfl_xor_sync(0xffffffffu, lmx, 1));
                lmx = fmaxf(lmx, __shfl_xor_sync(0xffffffffu, lmx, 2));
                lmx = fmaxf(lmx, __shfl_xor_sync(0xffffffffu, lmx, 4));
                float m_old = s_m[srow];
                float mx = fmaxf(m_old, lmx);
                p0.x = __expf(p0.x - mx); p0.y = __expf(p0.y - mx);
                p0.z = __expf(p0.z - mx); p0.w = __expf(p0.w - mx);
                p1.x = __expf(p1.x - mx); p1.y = __expf(p1.y - mx);
                p1.z = __expf(p1.z - mx); p1.w = __expf(p1.w - mx);
                *(float4*)&smP[srow * QST + spart * 8]     = p0;
                *(float4*)&smP[srow * QST + spart * 8 + 4] = p1;
                float ls = (p0.x + p0.y) + (p0.z + p0.w)
                         + (p1.x + p1.y) + (p1.z + p1.w);
                ls += __shfl_xor_sync(0xffffffffu, ls, 1);
                ls += __shfl_xor_sync(0xffffffffu, ls, 2);
                ls += __shfl_xor_sync(0xffffffffu, ls, 4);
                if (spart == 0) {
                    float alpha = __expf(m_old - mx);
                    s_a[srow] = alpha;
                    s_l[srow] = s_l[srow] * alpha + ls;
                    s_m[srow] = mx;
                }
            }
            __syncthreads();

            {
                u64 al0 = pack_dup(s_a[ty * 2]);
                u64 al1 = pack_dup(s_a[ty * 2 + 1]);
                mul2(acc[0][0], al0); mul2(acc[0][1], al0);
                mul2(acc[1][0], al1); mul2(acc[1][1], al1);
            }
#pragma unroll 8
            for (int j = 0; j < 64; j += 2) {
                float2 pr0 = *(const float2*)&smP[(ty * 2) * QST + j];
                float2 pr1 = *(const float2*)&smP[(ty * 2 + 1) * QST + j];
                ulonglong2 v0 = *(const ulonglong2*)&vbuf[j * 64 + tx * 4];
                ulonglong2 v1 = *(const ulonglong2*)&vbuf[(j + 1) * 64 + tx * 4];
                u64 p00 = pack_dup(pr0.x), p01 = pack_dup(pr0.y);
                u64 p10 = pack_dup(pr1.x), p11 = pack_dup(pr1.y);
                fma2(acc[0][0], p00, v0.x); fma2(acc[0][1], p00, v0.y);
                fma2(acc[1][0], p10, v0.x); fma2(acc[1][1], p10, v0.y);
                fma2(acc[0][0], p01, v1.x); fma2(acc[0][1], p01, v1.y);
                fma2(acc[1][0], p11, v1.x); fma2(acc[1][1], p11, v1.y);
            }
        }

#pragma unroll
        for (int i = 0; i < 2; i++) {
            const int row = ty * 2 + i;
            float inv = 1.0f / s_l[row];
            float2 o01 = unpack2(acc[i][0]);
            float2 o23 = unpack2(acc[i][1]);
            float4 o = make_float4(o01.x * inv, o01.y * inv,
                                   o23.x * inv, o23.y * inv);
            *(float4*)(out + (size_t)(b * T_SZ + q0 + row) * H_SZ + tx * 4) = o;
        }
    }
}

// ---------------------------------------------------------------------------
extern "C" void kernel_launch(void* const* d_in, const int* in_sizes, int n_in,
                              void* d_out, int out_size)
{
    const float* x  = (const float*)d_in[0];
    const float* Wq = (const float*)d_in[1];
    const float* Wk = (const float*)d_in[2];
    const float* Wv = (const float*)d_in[3];
    float* out = (float*)d_out;

    cudaFuncSetAttribute(qkv_mma_kernel, cudaFuncAttributeMaxDynamicSharedMemorySize,
                         QKV_SMEM);
    cudaFuncSetAttribute(attn_kernel, cudaFuncAttributeMaxDynamicSharedMemorySize,
                         ATTN_SMEM_BYTES);

    wsplit_kernel<<<dim3(16, 3), 256>>>(Wq, Wk, Wv);
    qkv_mma_kernel<<<MROWS / 128, 512, QKV_SMEM>>>(x);
    attn_kernel<<<dim3(16, B_SZ), 512, ATTN_SMEM_BYTES>>>(out);
}

// round 10
// speedup vs baseline: 4.0272x; 1.8091x over previous
#include <cuda_runtime.h>
#include <cuda_bf16.h>
#include <cstdint>
#include <cstddef>

#define B_SZ 8
#define T_SZ 2048
#define C_SZ 1024
#define H_SZ 64
#define MROWS (B_SZ * T_SZ)

typedef unsigned long long u64;

// ---------------- mma.sync helpers ----------------
__device__ __forceinline__ uint32_t smem_u32(const void* p) {
    uint32_t a;
    asm("{ .reg .u64 t; cvta.to.shared.u64 t, %1; cvt.u32.u64 %0, t; }" : "=r"(a) : "l"(p));
    return a;
}
__device__ __forceinline__ void ldsm_x4(uint32_t& r0, uint32_t& r1,
                                        uint32_t& r2, uint32_t& r3, uint32_t addr) {
    asm volatile("ldmatrix.sync.aligned.m8n8.x4.shared.b16 {%0,%1,%2,%3}, [%4];"
                 : "=r"(r0), "=r"(r1), "=r"(r2), "=r"(r3) : "r"(addr));
}
__device__ __forceinline__ void ldsm_x4_t(uint32_t& r0, uint32_t& r1,
                                          uint32_t& r2, uint32_t& r3, uint32_t addr) {
    asm volatile("ldmatrix.sync.aligned.m8n8.x4.trans.shared.b16 {%0,%1,%2,%3}, [%4];"
                 : "=r"(r0), "=r"(r1), "=r"(r2), "=r"(r3) : "r"(addr));
}
__device__ __forceinline__ void mma_bf16(float* c, const uint32_t* a,
                                         uint32_t b0, uint32_t b1) {
    asm volatile(
        "mma.sync.aligned.m16n8k16.row.col.f32.bf16.bf16.f32 "
        "{%0,%1,%2,%3}, {%4,%5,%6,%7}, {%8,%9}, {%0,%1,%2,%3};"
        : "+f"(c[0]), "+f"(c[1]), "+f"(c[2]), "+f"(c[3])
        : "r"(a[0]), "r"(a[1]), "r"(a[2]), "r"(a[3]), "r"(b0), "r"(b1));
}
// Split 8 floats into bf16 hi + lo vectors
__device__ __forceinline__ void cvt8(const float* v, uint4& Hu, uint4& Lu) {
    union { __nv_bfloat16 b[8]; uint4 u; } h, l;
#pragma unroll
    for (int i = 0; i < 8; i++) {
        __nv_bfloat16 hb = __float2bfloat16(v[i]);
        h.b[i] = hb;
        l.b[i] = __float2bfloat16(v[i] - __bfloat162float(hb));
    }
    Hu = h.u; Lu = l.u;
}

// ---------------- scratch ----------------
__device__ float g_q[MROWS * H_SZ];
__device__ float g_k[MROWS * H_SZ];
__device__ float g_v[MROWS * H_SZ];
__device__ __nv_bfloat16 g_wT_hi[3][64][C_SZ];   // [w][n][k]
__device__ __nv_bfloat16 g_wT_lo[3][64][C_SZ];

// ---------------------------------------------------------------------------
// Kernel 0: transpose + bf16 hi/lo split of the three weight matrices.
// ---------------------------------------------------------------------------
__global__ __launch_bounds__(256) void wsplit_kernel(
    const float* __restrict__ Wq, const float* __restrict__ Wk,
    const float* __restrict__ Wv)
{
    __shared__ float tile[64][65];
    const int w  = blockIdx.y;
    const int k0 = blockIdx.x * 64;
    const float* W = (w == 0) ? Wq : (w == 1) ? Wk : Wv;
    const int t = threadIdx.x;

    {
        int r = t >> 2, cs = (t & 3) * 16;
#pragma unroll
        for (int j = 0; j < 4; j++) {
            float4 v = *(const float4*)(W + (size_t)(k0 + r) * 64 + cs + j * 4);
            tile[r][cs + j * 4 + 0] = v.x; tile[r][cs + j * 4 + 1] = v.y;
            tile[r][cs + j * 4 + 2] = v.z; tile[r][cs + j * 4 + 3] = v.w;
        }
    }
    __syncthreads();
    {
        int n = t >> 2, ks = (t & 3) * 16;
        float vv[16];
#pragma unroll
        for (int i = 0; i < 16; i++) vv[i] = tile[ks + i][n];
        uint4 H0, L0, H1, L1;
        cvt8(vv, H0, L0); cvt8(vv + 8, H1, L1);
        *(uint4*)&g_wT_hi[w][n][k0 + ks]     = H0;
        *(uint4*)&g_wT_hi[w][n][k0 + ks + 8] = H1;
        *(uint4*)&g_wT_lo[w][n][k0 + ks]     = L0;
        *(uint4*)&g_wT_lo[w][n][k0 + ks + 8] = L1;
    }
}

// ---------------------------------------------------------------------------
// Kernel 1: QKV projections via mma.sync bf16 (unchanged, proven in R8).
// ---------------------------------------------------------------------------
#define A_HI_OFF 0
#define A_LO_OFF 18432
#define B_OFF    36864
#define QKV_SMEM (B_OFF + 6 * 9216)

__global__ __launch_bounds__(512) void qkv_mma_kernel(const float* __restrict__ x)
{
    extern __shared__ __align__(128) char smem_raw[];
    const uint32_t sb = smem_u32(smem_raw);
    const int t = threadIdx.x;
    const int wid = t >> 5, L = t & 31;
    const int mw = wid & 7, wsel = wid >> 3;
    const int m0 = blockIdx.x * 128;

    const uint32_t aRow  = mw * 16 + (L & 15);
    const uint32_t aHiB  = sb + A_HI_OFF + aRow * 144 + (L >> 4) * 16;
    const uint32_t aLoB  = sb + A_LO_OFF + aRow * 144 + (L >> 4) * 16;
    const uint32_t bLane = sb + B_OFF + ((L & 7) + ((L >> 4) & 1) * 8) * 144
                         + ((L >> 3) & 1) * 16;

    const int ar   = t >> 2;
    const int aseg = (t & 3) * 16;
    const float* xrow = x + (size_t)(m0 + ar) * C_SZ + aseg;

    const __nv_bfloat16* bsrc[6] = {
        &g_wT_hi[0][0][0], &g_wT_lo[0][0][0],
        &g_wT_hi[1][0][0], &g_wT_lo[1][0][0],
        &g_wT_hi[2][0][0], &g_wT_lo[2][0][0] };

    float acc[12][4];
#pragma unroll
    for (int i = 0; i < 12; i++)
#pragma unroll
        for (int j = 0; j < 4; j++) acc[i][j] = 0.0f;

    for (int kb = 0; kb < 16; kb++) {
#pragma unroll
        for (int c = 0; c < 2; c++) {
            float4 v0 = *(const float4*)(xrow + kb * 64 + c * 8);
            float4 v1 = *(const float4*)(xrow + kb * 64 + c * 8 + 4);
            float vv[8] = {v0.x, v0.y, v0.z, v0.w, v1.x, v1.y, v1.z, v1.w};
            uint4 H, Lo;
            cvt8(vv, H, Lo);
            const uint32_t off = ar * 144 + (aseg + c * 8) * 2;
            *(uint4*)(smem_raw + A_HI_OFF + off) = H;
            *(uint4*)(smem_raw + A_LO_OFF + off) = Lo;
        }
#pragma unroll
        for (int i = 0; i < 6; i++) {
            const int idx = t + i * 512;
            const int buf = idx >> 9;
            const int rem = idx & 511;
            const int n = rem >> 3, kc = rem & 7;
            uint4 v = *(const uint4*)(bsrc[buf] + (size_t)n * C_SZ + kb * 64 + kc * 8);
            *(uint4*)(smem_raw + B_OFF + buf * 9216 + n * 144 + kc * 16) = v;
        }
        __syncthreads();

#pragma unroll
        for (int ks = 0; ks < 4; ks++) {
            const uint32_t kbyte = ks * 32;
            uint32_t ah[4], al[4];
            ldsm_x4(ah[0], ah[1], ah[2], ah[3], aHiB + kbyte);
            ldsm_x4(al[0], al[1], al[2], al[3], aLoB + kbyte);
#pragma unroll
            for (int p = 0; p < 6; p++) {
                const int nc = wsel * 12 + 2 * p;
                const int w = nc >> 3, nt = nc & 7;
                const uint32_t bbase = bLane + (w * 2) * 9216 + nt * 1152 + kbyte;
                uint32_t bh[4], bl[4];
                ldsm_x4(bh[0], bh[1], bh[2], bh[3], bbase);
                ldsm_x4(bl[0], bl[1], bl[2], bl[3], bbase + 9216);
                mma_bf16(acc[2 * p],     ah, bh[0], bh[1]);
                mma_bf16(acc[2 * p],     al, bh[0], bh[1]);
                mma_bf16(acc[2 * p],     ah, bl[0], bl[1]);
                mma_bf16(acc[2 * p + 1], ah, bh[2], bh[3]);
                mma_bf16(acc[2 * p + 1], al, bh[2], bh[3]);
                mma_bf16(acc[2 * p + 1], ah, bl[2], bl[3]);
            }
        }
        __syncthreads();
    }

    float* outs[3] = {g_q, g_k, g_v};
    const int rrow = mw * 16 + (L >> 2);
    const int ccol = (L & 3) * 2;
#pragma unroll
    for (int ln = 0; ln < 12; ln++) {
        const int nc = wsel * 12 + ln;
        const int w = nc >> 3, nt = nc & 7;
        float* obase = outs[w] + (size_t)(m0 + rrow) * H_SZ + nt * 8 + ccol;
        *(float2*)obase              = make_float2(acc[ln][0], acc[ln][1]);
        *(float2*)(obase + 8 * H_SZ) = make_float2(acc[ln][2], acc[ln][3]);
    }
}

// ---------------------------------------------------------------------------
// Kernel 2: causal attention via mma.sync bf16 split hi/lo.
// Grid (16, 8), 256 threads (8 warps).  Q tile 64, paired (qb, 31-qb).
// Warp: mw = wid&3 -> rows mw*16..+16;  nw = wid>>2 -> cols nw*32..+32.
// ---------------------------------------------------------------------------
#define QH_OFF 0
#define QL_OFF 9216
#define KH_OFF 18432
#define KL_OFF 27648
#define VH_OFF 36864
#define VL_OFF 46080
#define PH_OFF 55296
#define PL_OFF 64512
#define S_OFF  73728                       // 64 x 68 fp32
#define STAT_OFF (S_OFF + 64 * 68 * 4)     // 91136
#define ATTN_SMEM (STAT_OFF + 3 * 64 * 4)  // 91904

__global__ __launch_bounds__(256) void attn_mma_kernel(float* __restrict__ out)
{
    extern __shared__ __align__(128) char smem_raw[];
    const uint32_t sb = smem_u32(smem_raw);
    float* smS = (float*)(smem_raw + S_OFF);
    float* s_m = (float*)(smem_raw + STAT_OFF);
    float* s_l = s_m + 64;
    float* s_a = s_l + 64;

    const int b = blockIdx.y;
    const int t = threadIdx.x;
    const int wid = t >> 5, L = t & 31;
    const int mw = wid & 3, nw = wid >> 2;
    const int lr = t >> 2;            // load row 0..63
    const int lc = (t & 3) * 16;      // load col segment (16 floats)
    const int srow = t >> 2;          // softmax row
    const int sp   = t & 3;           // softmax partition (16 cols)

    const float* qp = g_q + (size_t)b * T_SZ * H_SZ;
    const float* kp = g_k + (size_t)b * T_SZ * H_SZ;
    const float* vp = g_v + (size_t)b * T_SZ * H_SZ;

    // ldmatrix lane bases (byte offsets from sb)
    const uint32_t aQ = QH_OFF + (mw * 16 + (L & 15)) * 144 + (L >> 4) * 16;
    const uint32_t aP = PH_OFF + (mw * 16 + (L & 15)) * 144 + (L >> 4) * 16;
    const uint32_t bK = KH_OFF + ((L & 7) + ((L >> 4) & 1) * 8 + nw * 32) * 144
                      + ((L >> 3) & 1) * 16;
    const uint32_t vJ = (L & 7) + ((L >> 3) & 1) * 8;           // j-row within 16
    const uint32_t vC = (nw * 32 + ((L >> 4) & 1) * 8) * 2;     // v-col bytes

    // accumulator row/col mapping
    const int r0 = mw * 16 + (L >> 2);
    const int r1 = r0 + 8;
    const int cb = nw * 32 + (L & 3) * 2;

    for (int pass = 0; pass < 2; pass++) {
        const int qb = pass ? 31 - (int)blockIdx.x : (int)blockIdx.x;
        const int q0 = qb * 64;

        __syncthreads();   // protect smem from previous pass readers

        // ---- load + split Q tile
        {
            const float* qr = qp + (size_t)(q0 + lr) * H_SZ + lc;
            float vv[16];
            *(float4*)(vv)      = *(const float4*)(qr);
            *(float4*)(vv + 4)  = *(const float4*)(qr + 4);
            *(float4*)(vv + 8)  = *(const float4*)(qr + 8);
            *(float4*)(vv + 12) = *(const float4*)(qr + 12);
            uint4 H0, L0, H1, L1;
            cvt8(vv, H0, L0); cvt8(vv + 8, H1, L1);
            const uint32_t off = lr * 144 + lc * 2;
            *(uint4*)(smem_raw + QH_OFF + off)      = H0;
            *(uint4*)(smem_raw + QH_OFF + off + 16) = H1;
            *(uint4*)(smem_raw + QL_OFF + off)      = L0;
            *(uint4*)(smem_raw + QL_OFF + off + 16) = L1;
        }
        if (t < 64) { s_m[t] = -1e30f; s_l[t] = 0.0f; }

        float acc_o[4][4];
#pragma unroll
        for (int i = 0; i < 4; i++)
#pragma unroll
            for (int j = 0; j < 4; j++) acc_o[i][j] = 0.0f;

        // prefetch K tile 0
        float kf[16];
        {
            const float* kr = kp + (size_t)lr * H_SZ + lc;
            *(float4*)(kf)      = *(const float4*)(kr);
            *(float4*)(kf + 4)  = *(const float4*)(kr + 4);
            *(float4*)(kf + 8)  = *(const float4*)(kr + 8);
            *(float4*)(kf + 12) = *(const float4*)(kr + 12);
        }

        for (int kb = 0; kb <= qb; kb++) {
            const int k0 = kb * 64;

            // ---- step 1: split prefetched K into smem
            {
                uint4 H0, L0, H1, L1;
                cvt8(kf, H0, L0); cvt8(kf + 8, H1, L1);
                const uint32_t off = lr * 144 + lc * 2;
                *(uint4*)(smem_raw + KH_OFF + off)      = H0;
                *(uint4*)(smem_raw + KH_OFF + off + 16) = H1;
                *(uint4*)(smem_raw + KL_OFF + off)      = L0;
                *(uint4*)(smem_raw + KL_OFF + off + 16) = L1;
            }
            __syncthreads();   // step 2

            // ---- step 3: issue V loads (this tile) + next-K prefetch
            float vf[16];
            {
                const float* vr = vp + (size_t)(k0 + lr) * H_SZ + lc;
                *(float4*)(vf)      = *(const float4*)(vr);
                *(float4*)(vf + 4)  = *(const float4*)(vr + 4);
                *(float4*)(vf + 8)  = *(const float4*)(vr + 8);
                *(float4*)(vf + 12) = *(const float4*)(vr + 12);
            }
            if (kb < qb) {
                const float* kr = kp + (size_t)(k0 + 64 + lr) * H_SZ + lc;
                *(float4*)(kf)      = *(const float4*)(kr);
                *(float4*)(kf + 4)  = *(const float4*)(kr + 4);
                *(float4*)(kf + 8)  = *(const float4*)(kr + 8);
                *(float4*)(kf + 12) = *(const float4*)(kr + 12);
            }

            // ---- step 4: S = Q K^T  (3-term split)
            float s_acc[4][4];
#pragma unroll
            for (int i = 0; i < 4; i++)
#pragma unroll
                for (int j = 0; j < 4; j++) s_acc[i][j] = 0.0f;

#pragma unroll
            for (int ks = 0; ks < 4; ks++) {
                const uint32_t kbyte = ks * 32;
                uint32_t qh[4], ql[4];
                ldsm_x4(qh[0], qh[1], qh[2], qh[3], sb + aQ + kbyte);
                ldsm_x4(ql[0], ql[1], ql[2], ql[3], sb + aQ + 9216 + kbyte);
#pragma unroll
                for (int p = 0; p < 2; p++) {
                    const uint32_t bbase = sb + bK + p * 16 * 144 + kbyte;
                    uint32_t bh[4], bl[4];
                    ldsm_x4(bh[0], bh[1], bh[2], bh[3], bbase);
                    ldsm_x4(bl[0], bl[1], bl[2], bl[3], bbase + 9216);
                    mma_bf16(s_acc[2 * p],     qh, bh[0], bh[1]);
                    mma_bf16(s_acc[2 * p],     ql, bh[0], bh[1]);
                    mma_bf16(s_acc[2 * p],     qh, bl[0], bl[1]);
                    mma_bf16(s_acc[2 * p + 1], qh, bh[2], bh[3]);
                    mma_bf16(s_acc[2 * p + 1], ql, bh[2], bh[3]);
                    mma_bf16(s_acc[2 * p + 1], qh, bl[2], bl[3]);
                }
            }

            // ---- split V into smem (loads have landed by now)
            {
                uint4 H0, L0, H1, L1;
                cvt8(vf, H0, L0); cvt8(vf + 8, H1, L1);
                const uint32_t off = lr * 144 + lc * 2;
                *(uint4*)(smem_raw + VH_OFF + off)      = H0;
                *(uint4*)(smem_raw + VH_OFF + off + 16) = H1;
                *(uint4*)(smem_raw + VL_OFF + off)      = L0;
                *(uint4*)(smem_raw + VL_OFF + off + 16) = L1;
            }

            // ---- scale + mask + write S to smem (fp32)
            const bool diag = (kb == qb);
#pragma unroll
            for (int nt = 0; nt < 4; nt++) {
                const int c = cb + nt * 8;
                float2 v0 = make_float2(s_acc[nt][0] * 0.03125f, s_acc[nt][1] * 0.03125f);
                float2 v1 = make_float2(s_acc[nt][2] * 0.03125f, s_acc[nt][3] * 0.03125f);
                if (diag) {
                    if (c + 0 > r0) v0.x = -1e30f;
                    if (c + 1 > r0) v0.y = -1e30f;
                    if (c + 0 > r1) v1.x = -1e30f;
                    if (c + 1 > r1) v1.y = -1e30f;
                }
                *(float2*)&smS[r0 * 68 + c] = v0;
                *(float2*)&smS[r1 * 68 + c] = v1;
            }
            __syncthreads();   // step 5

            // ---- step 6: online softmax (4 threads/row, 16 cols each) -> P bf16 hi/lo
            {
                float p[16];
                *(float4*)(p)      = *(const float4*)&smS[srow * 68 + sp * 16];
                *(float4*)(p + 4)  = *(const float4*)&smS[srow * 68 + sp * 16 + 4];
                *(float4*)(p + 8)  = *(const float4*)&smS[srow * 68 + sp * 16 + 8];
                *(float4*)(p + 12) = *(const float4*)&smS[srow * 68 + sp * 16 + 12];
                float lmx = p[0];
#pragma unroll
                for (int i = 1; i < 16; i++) lmx = fmaxf(lmx, p[i]);
                lmx = fmaxf(lmx, __shfl_xor_sync(0xffffffffu, lmx, 1));
                lmx = fmaxf(lmx, __shfl_xor_sync(0xffffffffu, lmx, 2));
                const float m_old = s_m[srow];
                const float mx = fmaxf(m_old, lmx);
                float ls = 0.0f;
#pragma unroll
                for (int i = 0; i < 16; i++) { p[i] = __expf(p[i] - mx); ls += p[i]; }
                uint4 H0, L0, H1, L1;
                cvt8(p, H0, L0); cvt8(p + 8, H1, L1);
                const uint32_t off = srow * 144 + sp * 32;
                *(uint4*)(smem_raw + PH_OFF + off)      = H0;
                *(uint4*)(smem_raw + PH_OFF + off + 16) = H1;
                *(uint4*)(smem_raw + PL_OFF + off)      = L0;
                *(uint4*)(smem_raw + PL_OFF + off + 16) = L1;
                ls += __shfl_xor_sync(0xffffffffu, ls, 1);
                ls += __shfl_xor_sync(0xffffffffu, ls, 2);
                if (sp == 0) {
                    const float alpha = __expf(m_old - mx);
                    s_a[srow] = alpha;
                    s_l[srow] = s_l[srow] * alpha + ls;
                    s_m[srow] = mx;
                }
            }
            __syncthreads();   // step 6 end

            // ---- step 7: rescale acc_o, then acc_o += P V  (3-term split)
            {
                const float a0 = s_a[r0], a1 = s_a[r1];
#pragma unroll
                for (int nt = 0; nt < 4; nt++) {
                    acc_o[nt][0] *= a0; acc_o[nt][1] *= a0;
                    acc_o[nt][2] *= a1; acc_o[nt][3] *= a1;
                }
            }
#pragma unroll
            for (int ks = 0; ks < 4; ks++) {
                uint32_t ph[4], pl[4];
                ldsm_x4(ph[0], ph[1], ph[2], ph[3], sb + aP + ks * 32);
                ldsm_x4(pl[0], pl[1], pl[2], pl[3], sb + aP + 9216 + ks * 32);
#pragma unroll
                for (int p = 0; p < 2; p++) {
                    const uint32_t vaddr = sb + VH_OFF + (ks * 16 + vJ) * 144
                                         + vC + p * 32;
                    uint32_t vh[4], vl[4];
                    ldsm_x4_t(vh[0], vh[1], vh[2], vh[3], vaddr);
                    ldsm_x4_t(vl[0], vl[1], vl[2], vl[3], vaddr + 9216);
                    mma_bf16(acc_o[2 * p],     ph, vh[0], vh[1]);
                    mma_bf16(acc_o[2 * p],     pl, vh[0], vh[1]);
                    mma_bf16(acc_o[2 * p],     ph, vl[0], vl[1]);
                    mma_bf16(acc_o[2 * p + 1], ph, vh[2], vh[3]);
                    mma_bf16(acc_o[2 * p + 1], pl, vh[2], vh[3]);
                    mma_bf16(acc_o[2 * p + 1], ph, vl[2], vl[3]);
                }
            }
            // no trailing sync needed (next iter's step-2 and step-5 syncs
            // order all rewrites behind this iter's readers)
        }

        // ---- epilogue
        {
            const float inv0 = 1.0f / s_l[r0];
            const float inv1 = 1.0f / s_l[r1];
#pragma unroll
            for (int nt = 0; nt < 4; nt++) {
                const int c = cb + nt * 8;
                float* ob0 = out + (size_t)(b * T_SZ + q0 + r0) * H_SZ + c;
                float* ob1 = out + (size_t)(b * T_SZ + q0 + r1) * H_SZ + c;
                *(float2*)ob0 = make_float2(acc_o[nt][0] * inv0, acc_o[nt][1] * inv0);
                *(float2*)ob1 = make_float2(acc_o[nt][2] * inv1, acc_o[nt][3] * inv1);
            }
        }
    }
}

// ---------------------------------------------------------------------------
extern "C" void kernel_launch(void* const* d_in, const int* in_sizes, int n_in,
                              void* d_out, int out_size)
{
    const float* x  = (const float*)d_in[0];
    const float* Wq = (const float*)d_in[1];
    const float* Wk = (const float*)d_in[2];
    const float* Wv = (const float*)d_in[3];
    float* out = (float*)d_out;

    cudaFuncSetAttribute(qkv_mma_kernel, cudaFuncAttributeMaxDynamicSharedMemorySize,
                         QKV_SMEM);
    cudaFuncSetAttribute(attn_mma_kernel, cudaFuncAttributeMaxDynamicSharedMemorySize,
                         ATTN_SMEM);

    wsplit_kernel<<<dim3(16, 3), 256>>>(Wq, Wk, Wv);
    qkv_mma_kernel<<<MROWS / 128, 512, QKV_SMEM>>>(x);
    attn_mma_kernel<<<dim3(16, B_SZ), 256, ATTN_SMEM>>>(out);
}

// round 12
// speedup vs baseline: 4.3653x; 1.0839x over previous
#include <cuda_runtime.h>
#include <cuda_bf16.h>
#include <cstdint>
#include <cstddef>

#define B_SZ 8
#define T_SZ 2048
#define C_SZ 1024
#define H_SZ 64
#define MROWS (B_SZ * T_SZ)

typedef unsigned long long u64;

// ---------------- mma.sync helpers ----------------
__device__ __forceinline__ uint32_t smem_u32(const void* p) {
    uint32_t a;
    asm("{ .reg .u64 t; cvta.to.shared.u64 t, %1; cvt.u32.u64 %0, t; }" : "=r"(a) : "l"(p));
    return a;
}
__device__ __forceinline__ void ldsm_x4(uint32_t& r0, uint32_t& r1,
                                        uint32_t& r2, uint32_t& r3, uint32_t addr) {
    asm volatile("ldmatrix.sync.aligned.m8n8.x4.shared.b16 {%0,%1,%2,%3}, [%4];"
                 : "=r"(r0), "=r"(r1), "=r"(r2), "=r"(r3) : "r"(addr));
}
__device__ __forceinline__ void ldsm_x4_t(uint32_t& r0, uint32_t& r1,
                                          uint32_t& r2, uint32_t& r3, uint32_t addr) {
    asm volatile("ldmatrix.sync.aligned.m8n8.x4.trans.shared.b16 {%0,%1,%2,%3}, [%4];"
                 : "=r"(r0), "=r"(r1), "=r"(r2), "=r"(r3) : "r"(addr));
}
__device__ __forceinline__ void mma_bf16(float* c, const uint32_t* a,
                                         uint32_t b0, uint32_t b1) {
    asm volatile(
        "mma.sync.aligned.m16n8k16.row.col.f32.bf16.bf16.f32 "
        "{%0,%1,%2,%3}, {%4,%5,%6,%7}, {%8,%9}, {%0,%1,%2,%3};"
        : "+f"(c[0]), "+f"(c[1]), "+f"(c[2]), "+f"(c[3])
        : "r"(a[0]), "r"(a[1]), "r"(a[2]), "r"(a[3]), "r"(b0), "r"(b1));
}
__device__ __forceinline__ void cvt8(const float* v, uint4& Hu, uint4& Lu) {
    union { __nv_bfloat16 b[8]; uint4 u; } h, l;
#pragma unroll
    for (int i = 0; i < 8; i++) {
        __nv_bfloat16 hb = __float2bfloat16(v[i]);
        h.b[i] = hb;
        l.b[i] = __float2bfloat16(v[i] - __bfloat162float(hb));
    }
    Hu = h.u; Lu = l.u;
}
__device__ __forceinline__ void split2(float a, float b, uint32_t& hi, uint32_t& lo) {
    __nv_bfloat16 ah = __float2bfloat16(a), bh = __float2bfloat16(b);
    __nv_bfloat16 al = __float2bfloat16(a - __bfloat162float(ah));
    __nv_bfloat16 bl = __float2bfloat16(b - __bfloat162float(bh));
    union { __nv_bfloat16 b2[2]; uint32_t u; } H, L;
    H.b2[0] = ah; H.b2[1] = bh; L.b2[0] = al; L.b2[1] = bl;
    hi = H.u; lo = L.u;
}
__device__ __forceinline__ void cp16(uint32_t dst, const void* src) {
    asm volatile("cp.async.ca.shared.global [%0], [%1], 16;" :: "r"(dst), "l"(src));
}
__device__ __forceinline__ void cp_commit() {
    asm volatile("cp.async.commit_group;");
}
__device__ __forceinline__ void cp_wait_all() {
    asm volatile("cp.async.wait_group 0;");
}
__device__ __forceinline__ float qmax(float v) {
    v = fmaxf(v, __shfl_xor_sync(0xffffffffu, v, 1));
    v = fmaxf(v, __shfl_xor_sync(0xffffffffu, v, 2));
    return v;
}
__device__ __forceinline__ float qsum(float v) {
    v += __shfl_xor_sync(0xffffffffu, v, 1);
    v += __shfl_xor_sync(0xffffffffu, v, 2);
    return v;
}

// ---------------- scratch ----------------
__device__ float g_q[MROWS * H_SZ];
__device__ float g_k[MROWS * H_SZ];
__device__ float g_v[MROWS * H_SZ];
__device__ __nv_bfloat16 g_wT_hi[3][64][C_SZ];
__device__ __nv_bfloat16 g_wT_lo[3][64][C_SZ];

// ---------------------------------------------------------------------------
// Kernel 0: transpose + bf16 hi/lo split of the three weight matrices.
// ---------------------------------------------------------------------------
__global__ __launch_bounds__(256) void wsplit_kernel(
    const float* __restrict__ Wq, const float* __restrict__ Wk,
    const float* __restrict__ Wv)
{
    __shared__ float tile[64][65];
    const int w  = blockIdx.y;
    const int k0 = blockIdx.x * 64;
    const float* W = (w == 0) ? Wq : (w == 1) ? Wk : Wv;
    const int t = threadIdx.x;
    {
        int r = t >> 2, cs = (t & 3) * 16;
#pragma unroll
        for (int j = 0; j < 4; j++) {
            float4 v = *(const float4*)(W + (size_t)(k0 + r) * 64 + cs + j * 4);
            tile[r][cs + j * 4 + 0] = v.x; tile[r][cs + j * 4 + 1] = v.y;
            tile[r][cs + j * 4 + 2] = v.z; tile[r][cs + j * 4 + 3] = v.w;
        }
    }
    __syncthreads();
    {
        int n = t >> 2, ks = (t & 3) * 16;
        float vv[16];
#pragma unroll
        for (int i = 0; i < 16; i++) vv[i] = tile[ks + i][n];
        uint4 H0, L0, H1, L1;
        cvt8(vv, H0, L0); cvt8(vv + 8, H1, L1);
        *(uint4*)&g_wT_hi[w][n][k0 + ks]     = H0;
        *(uint4*)&g_wT_hi[w][n][k0 + ks + 8] = H1;
        *(uint4*)&g_wT_lo[w][n][k0 + ks]     = L0;
        *(uint4*)&g_wT_lo[w][n][k0 + ks + 8] = L1;
    }
}

// ---------------------------------------------------------------------------
// Kernel 1: QKV via mma.sync, double-buffered with cp.async.
// A[buf][hl]: buf*36864 + hl*18432;  B[buf][tile]: 73728 + buf*55296 + tile*9216
// ---------------------------------------------------------------------------
#define QKV_B_OFF 73728
#define QKV_SMEM  (QKV_B_OFF + 2 * 6 * 9216)

__global__ __launch_bounds__(512) void qkv_mma_kernel(const float* __restrict__ x)
{
    extern __shared__ __align__(128) char smem_raw[];
    const uint32_t sb = smem_u32(smem_raw);
    const int t = threadIdx.x;
    const int wid = t >> 5, L = t & 31;
    const int mw = wid & 7, wsel = wid >> 3;
    const int m0 = blockIdx.x * 128;

    const uint32_t aRowOff = (mw * 16 + (L & 15)) * 144 + (L >> 4) * 16;
    const uint32_t bLaneOff = ((L & 7) + ((L >> 4) & 1) * 8) * 144 + ((L >> 3) & 1) * 16;

    const int ar   = t >> 2;
    const int aseg = (t & 3) * 16;
    const float* xrow = x + (size_t)(m0 + ar) * C_SZ + aseg;
    const uint32_t aStoreOff = ar * 144 + aseg * 2;

    const __nv_bfloat16* bsrc[6] = {
        &g_wT_hi[0][0][0], &g_wT_lo[0][0][0],
        &g_wT_hi[1][0][0], &g_wT_lo[1][0][0],
        &g_wT_hi[2][0][0], &g_wT_lo[2][0][0] };
    // B copy indices (6 chunks of 16B per thread)
    int cbuf[6], cn[6], ckc[6];
#pragma unroll
    for (int i = 0; i < 6; i++) {
        const int idx = t + i * 512;
        cbuf[i] = idx >> 9;
        cn[i]   = (idx & 511) >> 3;
        ckc[i]  = idx & 7;
    }

    float acc[12][4];
#pragma unroll
    for (int i = 0; i < 12; i++)
#pragma unroll
        for (int j = 0; j < 4; j++) acc[i][j] = 0.0f;

    float xr[16];
    // ---- prologue: kb = 0
    *(float4*)(xr)      = *(const float4*)(xrow);
    *(float4*)(xr + 4)  = *(const float4*)(xrow + 4);
    *(float4*)(xr + 8)  = *(const float4*)(xrow + 8);
    *(float4*)(xr + 12) = *(const float4*)(xrow + 12);
#pragma unroll
    for (int i = 0; i < 6; i++)
        cp16(sb + QKV_B_OFF + cbuf[i] * 9216 + cn[i] * 144 + ckc[i] * 16,
             bsrc[cbuf[i]] + (size_t)cn[i] * C_SZ + ckc[i] * 8);
    cp_commit();
    {
        uint4 H0, L0, H1, L1;
        cvt8(xr, H0, L0); cvt8(xr + 8, H1, L1);
        *(uint4*)(smem_raw + aStoreOff)              = H0;
        *(uint4*)(smem_raw + aStoreOff + 16)         = H1;
        *(uint4*)(smem_raw + 18432 + aStoreOff)      = L0;
        *(uint4*)(smem_raw + 18432 + aStoreOff + 16) = L1;
    }
    // load x regs for kb = 1
    *(float4*)(xr)      = *(const float4*)(xrow + 64);
    *(float4*)(xr + 4)  = *(const float4*)(xrow + 68);
    *(float4*)(xr + 8)  = *(const float4*)(xrow + 72);
    *(float4*)(xr + 12) = *(const float4*)(xrow + 76);
    cp_wait_all();
    __syncthreads();

    for (int kb = 0; kb < 16; kb++) {
        const int cur = kb & 1, nxt = cur ^ 1;
        // issue next B copies (into nxt buffers) — overlaps MMA below
        if (kb < 15) {
#pragma unroll
            for (int i = 0; i < 6; i++)
                cp16(sb + QKV_B_OFF + nxt * 55296 + cbuf[i] * 9216 + cn[i] * 144 + ckc[i] * 16,
                     bsrc[cbuf[i]] + (size_t)cn[i] * C_SZ + (kb + 1) * 64 + ckc[i] * 8);
            cp_commit();
        }

        // ---- MMA on cur
        const uint32_t aHi = sb + cur * 36864 + aRowOff;
        const uint32_t aLo = aHi + 18432;
        const uint32_t bB  = sb + QKV_B_OFF + cur * 55296 + bLaneOff;
#pragma unroll
        for (int ks = 0; ks < 4; ks++) {
            const uint32_t kbyte = ks * 32;
            uint32_t ah[4], al[4];
            ldsm_x4(ah[0], ah[1], ah[2], ah[3], aHi + kbyte);
            ldsm_x4(al[0], al[1], al[2], al[3], aLo + kbyte);
#pragma unroll
            for (int p = 0; p < 6; p++) {
                const int nc = wsel * 12 + 2 * p;
                const int w = nc >> 3, nt = nc & 7;
                const uint32_t bbase = bB + (w * 2) * 9216 + nt * 1152 + kbyte;
                uint32_t bh[4], bl[4];
                ldsm_x4(bh[0], bh[1], bh[2], bh[3], bbase);
                ldsm_x4(bl[0], bl[1], bl[2], bl[3], bbase + 9216);
                mma_bf16(acc[2 * p],     ah, bh[0], bh[1]);
                mma_bf16(acc[2 * p],     al, bh[0], bh[1]);
                mma_bf16(acc[2 * p],     ah, bl[0], bl[1]);
                mma_bf16(acc[2 * p + 1], ah, bh[2], bh[3]);
                mma_bf16(acc[2 * p + 1], al, bh[2], bh[3]);
                mma_bf16(acc[2 * p + 1], ah, bl[2], bl[3]);
            }
        }

        // ---- store next x into A[nxt]; then prefetch x for kb+2
        if (kb < 15) {
            uint4 H0, L0, H1, L1;
            cvt8(xr, H0, L0); cvt8(xr + 8, H1, L1);
            char* abase = smem_raw + nxt * 36864;
            *(uint4*)(abase + aStoreOff)              = H0;
            *(uint4*)(abase + aStoreOff + 16)         = H1;
            *(uint4*)(abase + 18432 + aStoreOff)      = L0;
            *(uint4*)(abase + 18432 + aStoreOff + 16) = L1;
            if (kb < 14) {
                const float* xs = xrow + (kb + 2) * 64;
                *(float4*)(xr)      = *(const float4*)(xs);
                *(float4*)(xr + 4)  = *(const float4*)(xs + 4);
                *(float4*)(xr + 8)  = *(const float4*)(xs + 8);
                *(float4*)(xr + 12) = *(const float4*)(xs + 12);
            }
        }
        cp_wait_all();
        __syncthreads();
    }

    float* outs[3] = {g_q, g_k, g_v};
    const int rrow = mw * 16 + (L >> 2);
    const int ccol = (L & 3) * 2;
#pragma unroll
    for (int ln = 0; ln < 12; ln++) {
        const int nc = wsel * 12 + ln;
        const int w = nc >> 3, nt = nc & 7;
        float* obase = outs[w] + (size_t)(m0 + rrow) * H_SZ + nt * 8 + ccol;
        *(float2*)obase              = make_float2(acc[ln][0], acc[ln][1]);
        *(float2*)(obase + 8 * H_SZ) = make_float2(acc[ln][2], acc[ln][3]);
    }
}

// ---------------------------------------------------------------------------
// Kernel 2: causal attention, 512 threads (16 warps), register softmax.
// Warp: mw = wid&3 (16-row band), nw = wid>>2 (16 kv-cols / 16 v-cols).
// ---------------------------------------------------------------------------
#define AQH 0
#define AQL 9216
#define AKH 18432
#define AKL 27648
#define AVH 36864
#define AVL 46080
#define APH 55296
#define APL 64512
#define AEX 73728                       // float2 [64][4]
#define AST 75776                       // s_m[64], s_l[64]
#define ATTN_SMEM (AST + 2 * 64 * 4)    // 76288

__global__ __launch_bounds__(512) void attn_mma_kernel(float* __restrict__ out)
{
    extern __shared__ __align__(128) char smem_raw[];
    const uint32_t sb = smem_u32(smem_raw);
    float2* smEx = (float2*)(smem_raw + AEX);
    float* s_m = (float*)(smem_raw + AST);
    float* s_l = s_m + 64;

    const int b = blockIdx.y;
    const int t = threadIdx.x;
    const int wid = t >> 5, L = t & 31;
    const int mw = wid & 3, nw = wid >> 2;
    const int lr = t >> 3;            // load row 0..63
    const int lc = (t & 7) * 8;       // 8 floats

    const float* qp = g_q + (size_t)b * T_SZ * H_SZ;
    const float* kp = g_k + (size_t)b * T_SZ * H_SZ;
    const float* vp = g_v + (size_t)b * T_SZ * H_SZ;

    const uint32_t aQ = AQH + (mw * 16 + (L & 15)) * 144 + (L >> 4) * 16;
    const uint32_t aP = APH + (mw * 16 + (L & 15)) * 144 + (L >> 4) * 16;
    const uint32_t bK = AKH + ((L & 7) + ((L >> 4) & 1) * 8 + nw * 16) * 144
                      + ((L >> 3) & 1) * 16;
    const uint32_t vJ = (L & 7) + ((L >> 3) & 1) * 8;
    const uint32_t vC = (nw * 16 + ((L >> 4) & 1) * 8) * 2;

    const int r0 = mw * 16 + (L >> 2);
    const int r1 = r0 + 8;
    const int cbase = nw * 16 + (L & 3) * 2;
    const uint32_t ldOff = lr * 144 + lc * 2;

    for (int pass = 0; pass < 2; pass++) {
        const int qb = pass ? 31 - (int)blockIdx.x : (int)blockIdx.x;
        const int q0 = qb * 64;

        __syncthreads();   // protect smem/stats from previous pass

        // ---- load + split Q (8 floats/thread)
        {
            const float* qr = qp + (size_t)(q0 + lr) * H_SZ + lc;
            float vv[8];
            *(float4*)(vv)     = *(const float4*)(qr);
            *(float4*)(vv + 4) = *(const float4*)(qr + 4);
            uint4 H, Lo;
            cvt8(vv, H, Lo);
            *(uint4*)(smem_raw + AQH + ldOff) = H;
            *(uint4*)(smem_raw + AQL + ldOff) = Lo;
        }
        if (t < 64) { s_m[t] = -1e30f; s_l[t] = 0.0f; }

        float acc_o[2][4];
#pragma unroll
        for (int i = 0; i < 2; i++)
#pragma unroll
            for (int j = 0; j < 4; j++) acc_o[i][j] = 0.0f;

        // prefetch K tile 0
        float kf[8];
        {
            const float* kr = kp + (size_t)lr * H_SZ + lc;
            *(float4*)(kf)     = *(const float4*)(kr);
            *(float4*)(kf + 4) = *(const float4*)(kr + 4);
        }

        for (int kb = 0; kb <= qb; kb++) {
            const int k0 = kb * 64;

            // K split store
            {
                uint4 H, Lo;
                cvt8(kf, H, Lo);
                *(uint4*)(smem_raw + AKH + ldOff) = H;
                *(uint4*)(smem_raw + AKL + ldOff) = Lo;
            }
            __syncthreads();   // S1: K (and Q, stats-init) ready

            // V load (this tile) + next K prefetch
            float vf[8];
            {
                const float* vr = vp + (size_t)(k0 + lr) * H_SZ + lc;
                *(float4*)(vf)     = *(const float4*)(vr);
                *(float4*)(vf + 4) = *(const float4*)(vr + 4);
            }
            if (kb < qb) {
                const float* kr = kp + (size_t)(k0 + 64 + lr) * H_SZ + lc;
                *(float4*)(kf)     = *(const float4*)(kr);
                *(float4*)(kf + 4) = *(const float4*)(kr + 4);
            }

            // ---- S = Q K^T (3-term), warp tile 16x16
            float s2[2][4];
#pragma unroll
            for (int i = 0; i < 2; i++)
#pragma unroll
                for (int j = 0; j < 4; j++) s2[i][j] = 0.0f;
#pragma unroll
            for (int ks = 0; ks < 4; ks++) {
                const uint32_t kbyte = ks * 32;
                uint32_t qh[4], ql[4], bh[4], bl[4];
                ldsm_x4(qh[0], qh[1], qh[2], qh[3], sb + aQ + kbyte);
                ldsm_x4(ql[0], ql[1], ql[2], ql[3], sb + aQ + 9216 + kbyte);
                ldsm_x4(bh[0], bh[1], bh[2], bh[3], sb + bK + kbyte);
                ldsm_x4(bl[0], bl[1], bl[2], bl[3], sb + bK + 9216 + kbyte);
                mma_bf16(s2[0], qh, bh[0], bh[1]);
                mma_bf16(s2[0], ql, bh[0], bh[1]);
                mma_bf16(s2[0], qh, bl[0], bl[1]);
                mma_bf16(s2[1], qh, bh[2], bh[3]);
                mma_bf16(s2[1], ql, bh[2], bh[3]);
                mma_bf16(s2[1], qh, bl[2], bl[3]);
            }

            // V split store (readers gated by S3)
            {
                uint4 H, Lo;
                cvt8(vf, H, Lo);
                *(uint4*)(smem_raw + AVH + ldOff) = H;
                *(uint4*)(smem_raw + AVL + ldOff) = Lo;
            }

            // ---- scale + mask in registers
            const bool diag = (kb == qb);
#pragma unroll
            for (int nt = 0; nt < 2; nt++) {
                const int c = cbase + nt * 8;
                s2[nt][0] *= 0.03125f; s2[nt][1] *= 0.03125f;
                s2[nt][2] *= 0.03125f; s2[nt][3] *= 0.03125f;
                if (diag) {
                    if (c + 0 > r0) s2[nt][0] = -1e30f;
                    if (c + 1 > r0) s2[nt][1] = -1e30f;
                    if (c + 0 > r1) s2[nt][2] = -1e30f;
                    if (c + 1 > r1) s2[nt][3] = -1e30f;
                }
            }

            // ---- per-warp partial softmax over 16 cols
            float pm0 = fmaxf(fmaxf(s2[0][0], s2[0][1]), fmaxf(s2[1][0], s2[1][1]));
            float pm1 = fmaxf(fmaxf(s2[0][2], s2[0][3]), fmaxf(s2[1][2], s2[1][3]));
            pm0 = qmax(pm0); pm1 = qmax(pm1);
#pragma unroll
            for (int nt = 0; nt < 2; nt++) {
                s2[nt][0] = __expf(s2[nt][0] - pm0);
                s2[nt][1] = __expf(s2[nt][1] - pm0);
                s2[nt][2] = __expf(s2[nt][2] - pm1);
                s2[nt][3] = __expf(s2[nt][3] - pm1);
            }
            float ps0 = qsum(s2[0][0] + s2[0][1] + s2[1][0] + s2[1][1]);
            float ps1 = qsum(s2[0][2] + s2[0][3] + s2[1][2] + s2[1][3]);
            if ((L & 3) == 0) {
                smEx[r0 * 4 + nw] = make_float2(pm0, ps0);
                smEx[r1 * 4 + nw] = make_float2(pm1, ps1);
            }
            __syncthreads();   // S2: exchange

            // ---- combine (all lanes redundantly)
            float mx0, mx1, l0, l1, alpha0, alpha1, f0, f1;
            {
                const float mo0 = s_m[r0], lo0 = s_l[r0];
                const float mo1 = s_m[r1], lo1 = s_l[r1];
                float2 e0[4], e1[4];
#pragma unroll
                for (int i = 0; i < 4; i++) { e0[i] = smEx[r0 * 4 + i]; e1[i] = smEx[r1 * 4 + i]; }
                mx0 = mo0; mx1 = mo1;
#pragma unroll
                for (int i = 0; i < 4; i++) { mx0 = fmaxf(mx0, e0[i].x); mx1 = fmaxf(mx1, e1[i].x); }
                alpha0 = __expf(mo0 - mx0); alpha1 = __expf(mo1 - mx1);
                l0 = lo0 * alpha0; l1 = lo1 * alpha1;
#pragma unroll
                for (int i = 0; i < 4; i++) {
                    l0 += e0[i].y * __expf(e0[i].x - mx0);
                    l1 += e1[i].y * __expf(e1[i].x - mx1);
                }
                f0 = __expf(pm0 - mx0); f1 = __expf(pm1 - mx1);
            }

            // ---- P = e * f -> bf16 hi/lo, write to smem
#pragma unroll
            for (int nt = 0; nt < 2; nt++) {
                const int c = cbase + nt * 8;
                uint32_t hi, lo;
                split2(s2[nt][0] * f0, s2[nt][1] * f0, hi, lo);
                *(uint32_t*)(smem_raw + APH + r0 * 144 + c * 2) = hi;
                *(uint32_t*)(smem_raw + APL + r0 * 144 + c * 2) = lo;
                split2(s2[nt][2] * f1, s2[nt][3] * f1, hi, lo);
                *(uint32_t*)(smem_raw + APH + r1 * 144 + c * 2) = hi;
                *(uint32_t*)(smem_raw + APL + r1 * 144 + c * 2) = lo;
            }
            __syncthreads();   // S3: P + V ready

            // deferred stats write (no readers between S2 and S3 anymore)
            if (nw == 0 && (L & 3) == 0) {
                s_m[r0] = mx0; s_l[r0] = l0;
                s_m[r1] = mx1; s_l[r1] = l1;
            }

            // ---- rescale + O += P V (3-term)
#pragma unroll
            for (int nt = 0; nt < 2; nt++) {
                acc_o[nt][0] *= alpha0; acc_o[nt][1] *= alpha0;
                acc_o[nt][2] *= alpha1; acc_o[nt][3] *= alpha1;
            }
#pragma unroll
            for (int ks = 0; ks < 4; ks++) {
                uint32_t ph[4], pl[4], vh[4], vl[4];
                ldsm_x4(ph[0], ph[1], ph[2], ph[3], sb + aP + ks * 32);
                ldsm_x4(pl[0], pl[1], pl[2], pl[3], sb + aP + 9216 + ks * 32);
                const uint32_t vaddr = sb + AVH + (ks * 16 + vJ) * 144 + vC;
                ldsm_x4_t(vh[0], vh[1], vh[2], vh[3], vaddr);
                ldsm_x4_t(vl[0], vl[1], vl[2], vl[3], vaddr + 9216);
                mma_bf16(acc_o[0], ph, vh[0], vh[1]);
                mma_bf16(acc_o[0], pl, vh[0], vh[1]);
                mma_bf16(acc_o[0], ph, vl[0], vl[1]);
                mma_bf16(acc_o[1], ph, vh[2], vh[3]);
                mma_bf16(acc_o[1], pl, vh[2], vh[3]);
                mma_bf16(acc_o[1], ph, vl[2], vl[3]);
            }
        }

        __syncthreads();   // stats writes visible for epilogue
        {
            const float inv0 = 1.0f / s_l[r0];
            const float inv1 = 1.0f / s_l[r1];
#pragma unroll
            for (int nt = 0; nt < 2; nt++) {
                const int c = cbase + nt * 8;
                float* ob0 = out + (size_t)(b * T_SZ + q0 + r0) * H_SZ + c;
                float* ob1 = out + (size_t)(b * T_SZ + q0 + r1) * H_SZ + c;
                *(float2*)ob0 = make_float2(acc_o[nt][0] * inv0, acc_o[nt][1] * inv0);
                *(float2*)ob1 = make_float2(acc_o[nt][2] * inv1, acc_o[nt][3] * inv1);
            }
        }
    }
}

// ---------------------------------------------------------------------------
extern "C" void kernel_launch(void* const* d_in, const int* in_sizes, int n_in,
                              void* d_out, int out_size)
{
    const float* x  = (const float*)d_in[0];
    const float* Wq = (const float*)d_in[1];
    const float* Wk = (const float*)d_in[2];
    const float* Wv = (const float*)d_in[3];
    float* out = (float*)d_out;

    cudaFuncSetAttribute(qkv_mma_kernel, cudaFuncAttributeMaxDynamicSharedMemorySize,
                         QKV_SMEM);
    cudaFuncSetAttribute(attn_mma_kernel, cudaFuncAttributeMaxDynamicSharedMemorySize,
                         ATTN_SMEM);

    wsplit_kernel<<<dim3(16, 3), 256>>>(Wq, Wk, Wv);
    qkv_mma_kernel<<<MROWS / 128, 512, QKV_SMEM>>>(x);
    attn_mma_kernel<<<dim3(16, B_SZ), 512, ATTN_SMEM>>>(out);
}

// round 13
// speedup vs baseline: 4.5998x; 1.0537x over previous
#include <cuda_runtime.h>
#include <cuda_bf16.h>
#include <cstdint>
#include <cstddef>

#define B_SZ 8
#define T_SZ 2048
#define C_SZ 1024
#define H_SZ 64
#define MROWS (B_SZ * T_SZ)

typedef unsigned long long u64;

// ---------------- mma.sync helpers ----------------
__device__ __forceinline__ uint32_t smem_u32(const void* p) {
    uint32_t a;
    asm("{ .reg .u64 t; cvta.to.shared.u64 t, %1; cvt.u32.u64 %0, t; }" : "=r"(a) : "l"(p));
    return a;
}
__device__ __forceinline__ void ldsm_x4(uint32_t& r0, uint32_t& r1,
                                        uint32_t& r2, uint32_t& r3, uint32_t addr) {
    asm volatile("ldmatrix.sync.aligned.m8n8.x4.shared.b16 {%0,%1,%2,%3}, [%4];"
                 : "=r"(r0), "=r"(r1), "=r"(r2), "=r"(r3) : "r"(addr));
}
__device__ __forceinline__ void ldsm_x4_t(uint32_t& r0, uint32_t& r1,
                                          uint32_t& r2, uint32_t& r3, uint32_t addr) {
    asm volatile("ldmatrix.sync.aligned.m8n8.x4.trans.shared.b16 {%0,%1,%2,%3}, [%4];"
                 : "=r"(r0), "=r"(r1), "=r"(r2), "=r"(r3) : "r"(addr));
}
__device__ __forceinline__ void mma_bf16(float* c, const uint32_t* a,
                                         uint32_t b0, uint32_t b1) {
    asm volatile(
        "mma.sync.aligned.m16n8k16.row.col.f32.bf16.bf16.f32 "
        "{%0,%1,%2,%3}, {%4,%5,%6,%7}, {%8,%9}, {%0,%1,%2,%3};"
        : "+f"(c[0]), "+f"(c[1]), "+f"(c[2]), "+f"(c[3])
        : "r"(a[0]), "r"(a[1]), "r"(a[2]), "r"(a[3]), "r"(b0), "r"(b1));
}
__device__ __forceinline__ void cvt8(const float* v, uint4& Hu, uint4& Lu) {
    union { __nv_bfloat16 b[8]; uint4 u; } h, l;
#pragma unroll
    for (int i = 0; i < 8; i++) {
        __nv_bfloat16 hb = __float2bfloat16(v[i]);
        h.b[i] = hb;
        l.b[i] = __float2bfloat16(v[i] - __bfloat162float(hb));
    }
    Hu = h.u; Lu = l.u;
}
__device__ __forceinline__ void split2(float a, float b, uint32_t& hi, uint32_t& lo) {
    __nv_bfloat16 ah = __float2bfloat16(a), bh = __float2bfloat16(b);
    __nv_bfloat16 al = __float2bfloat16(a - __bfloat162float(ah));
    __nv_bfloat16 bl = __float2bfloat16(b - __bfloat162float(bh));
    union { __nv_bfloat16 b2[2]; uint32_t u; } H, L;
    H.b2[0] = ah; H.b2[1] = bh; L.b2[0] = al; L.b2[1] = bl;
    hi = H.u; lo = L.u;
}
__device__ __forceinline__ void cp16(uint32_t dst, const void* src) {
    asm volatile("cp.async.ca.shared.global [%0], [%1], 16;" :: "r"(dst), "l"(src));
}
__device__ __forceinline__ void cp_commit() {
    asm volatile("cp.async.commit_group;");
}
__device__ __forceinline__ void cp_wait_all() {
    asm volatile("cp.async.wait_group 0;");
}
__device__ __forceinline__ float qmax(float v) {
    v = fmaxf(v, __shfl_xor_sync(0xffffffffu, v, 1));
    v = fmaxf(v, __shfl_xor_sync(0xffffffffu, v, 2));
    return v;
}
__device__ __forceinline__ float qsum(float v) {
    v += __shfl_xor_sync(0xffffffffu, v, 1);
    v += __shfl_xor_sync(0xffffffffu, v, 2);
    return v;
}

// ---------------- scratch ----------------
__device__ float g_q[MROWS * H_SZ];
__device__ float g_k[MROWS * H_SZ];
__device__ float g_v[MROWS * H_SZ];
__device__ __nv_bfloat16 g_wT_hi[3][64][C_SZ];
__device__ __nv_bfloat16 g_wT_lo[3][64][C_SZ];

// ---------------------------------------------------------------------------
// Kernel 0: transpose + bf16 hi/lo split of the three weight matrices.
// ---------------------------------------------------------------------------
__global__ __launch_bounds__(256) void wsplit_kernel(
    const float* __restrict__ Wq, const float* __restrict__ Wk,
    const float* __restrict__ Wv)
{
    __shared__ float tile[64][65];
    const int w  = blockIdx.y;
    const int k0 = blockIdx.x * 64;
    const float* W = (w == 0) ? Wq : (w == 1) ? Wk : Wv;
    const int t = threadIdx.x;
    {
        int r = t >> 2, cs = (t & 3) * 16;
#pragma unroll
        for (int j = 0; j < 4; j++) {
            float4 v = *(const float4*)(W + (size_t)(k0 + r) * 64 + cs + j * 4);
            tile[r][cs + j * 4 + 0] = v.x; tile[r][cs + j * 4 + 1] = v.y;
            tile[r][cs + j * 4 + 2] = v.z; tile[r][cs + j * 4 + 3] = v.w;
        }
    }
    __syncthreads();
    {
        int n = t >> 2, ks = (t & 3) * 16;
        float vv[16];
#pragma unroll
        for (int i = 0; i < 16; i++) vv[i] = tile[ks + i][n];
        uint4 H0, L0, H1, L1;
        cvt8(vv, H0, L0); cvt8(vv + 8, H1, L1);
        *(uint4*)&g_wT_hi[w][n][k0 + ks]     = H0;
        *(uint4*)&g_wT_hi[w][n][k0 + ks + 8] = H1;
        *(uint4*)&g_wT_lo[w][n][k0 + ks]     = L0;
        *(uint4*)&g_wT_lo[w][n][k0 + ks + 8] = L1;
    }
}

// ---------------------------------------------------------------------------
// Kernel 1: QKV via mma.sync, double-buffered with cp.async (proven R12).
// ---------------------------------------------------------------------------
#define QKV_B_OFF 73728
#define QKV_SMEM  (QKV_B_OFF + 2 * 6 * 9216)

__global__ __launch_bounds__(512) void qkv_mma_kernel(const float* __restrict__ x)
{
    extern __shared__ __align__(128) char smem_raw[];
    const uint32_t sb = smem_u32(smem_raw);
    const int t = threadIdx.x;
    const int wid = t >> 5, L = t & 31;
    const int mw = wid & 7, wsel = wid >> 3;
    const int m0 = blockIdx.x * 128;

    const uint32_t aRowOff = (mw * 16 + (L & 15)) * 144 + (L >> 4) * 16;
    const uint32_t bLaneOff = ((L & 7) + ((L >> 4) & 1) * 8) * 144 + ((L >> 3) & 1) * 16;

    const int ar   = t >> 2;
    const int aseg = (t & 3) * 16;
    const float* xrow = x + (size_t)(m0 + ar) * C_SZ + aseg;
    const uint32_t aStoreOff = ar * 144 + aseg * 2;

    const __nv_bfloat16* bsrc[6] = {
        &g_wT_hi[0][0][0], &g_wT_lo[0][0][0],
        &g_wT_hi[1][0][0], &g_wT_lo[1][0][0],
        &g_wT_hi[2][0][0], &g_wT_lo[2][0][0] };
    int cbuf[6], cn[6], ckc[6];
#pragma unroll
    for (int i = 0; i < 6; i++) {
        const int idx = t + i * 512;
        cbuf[i] = idx >> 9;
        cn[i]   = (idx & 511) >> 3;
        ckc[i]  = idx & 7;
    }

    float acc[12][4];
#pragma unroll
    for (int i = 0; i < 12; i++)
#pragma unroll
        for (int j = 0; j < 4; j++) acc[i][j] = 0.0f;

    float xr[16];
    *(float4*)(xr)      = *(const float4*)(xrow);
    *(float4*)(xr + 4)  = *(const float4*)(xrow + 4);
    *(float4*)(xr + 8)  = *(const float4*)(xrow + 8);
    *(float4*)(xr + 12) = *(const float4*)(xrow + 12);
#pragma unroll
    for (int i = 0; i < 6; i++)
        cp16(sb + QKV_B_OFF + cbuf[i] * 9216 + cn[i] * 144 + ckc[i] * 16,
             bsrc[cbuf[i]] + (size_t)cn[i] * C_SZ + ckc[i] * 8);
    cp_commit();
    {
        uint4 H0, L0, H1, L1;
        cvt8(xr, H0, L0); cvt8(xr + 8, H1, L1);
        *(uint4*)(smem_raw + aStoreOff)              = H0;
        *(uint4*)(smem_raw + aStoreOff + 16)         = H1;
        *(uint4*)(smem_raw + 18432 + aStoreOff)      = L0;
        *(uint4*)(smem_raw + 18432 + aStoreOff + 16) = L1;
    }
    *(float4*)(xr)      = *(const float4*)(xrow + 64);
    *(float4*)(xr + 4)  = *(const float4*)(xrow + 68);
    *(float4*)(xr + 8)  = *(const float4*)(xrow + 72);
    *(float4*)(xr + 12) = *(const float4*)(xrow + 76);
    cp_wait_all();
    __syncthreads();

    for (int kb = 0; kb < 16; kb++) {
        const int cur = kb & 1, nxt = cur ^ 1;
        if (kb < 15) {
#pragma unroll
            for (int i = 0; i < 6; i++)
                cp16(sb + QKV_B_OFF + nxt * 55296 + cbuf[i] * 9216 + cn[i] * 144 + ckc[i] * 16,
                     bsrc[cbuf[i]] + (size_t)cn[i] * C_SZ + (kb + 1) * 64 + ckc[i] * 8);
            cp_commit();
        }

        const uint32_t aHi = sb + cur * 36864 + aRowOff;
        const uint32_t aLo = aHi + 18432;
        const uint32_t bB  = sb + QKV_B_OFF + cur * 55296 + bLaneOff;
#pragma unroll
        for (int ks = 0; ks < 4; ks++) {
            const uint32_t kbyte = ks * 32;
            uint32_t ah[4], al[4];
            ldsm_x4(ah[0], ah[1], ah[2], ah[3], aHi + kbyte);
            ldsm_x4(al[0], al[1], al[2], al[3], aLo + kbyte);
#pragma unroll
            for (int p = 0; p < 6; p++) {
                const int nc = wsel * 12 + 2 * p;
                const int w = nc >> 3, nt = nc & 7;
                const uint32_t bbase = bB + (w * 2) * 9216 + nt * 1152 + kbyte;
                uint32_t bh[4], bl[4];
                ldsm_x4(bh[0], bh[1], bh[2], bh[3], bbase);
                ldsm_x4(bl[0], bl[1], bl[2], bl[3], bbase + 9216);
                mma_bf16(acc[2 * p],     ah, bh[0], bh[1]);
                mma_bf16(acc[2 * p],     al, bh[0], bh[1]);
                mma_bf16(acc[2 * p],     ah, bl[0], bl[1]);
                mma_bf16(acc[2 * p + 1], ah, bh[2], bh[3]);
                mma_bf16(acc[2 * p + 1], al, bh[2], bh[3]);
                mma_bf16(acc[2 * p + 1], ah, bl[2], bl[3]);
            }
        }

        if (kb < 15) {
            uint4 H0, L0, H1, L1;
            cvt8(xr, H0, L0); cvt8(xr + 8, H1, L1);
            char* abase = smem_raw + nxt * 36864;
            *(uint4*)(abase + aStoreOff)              = H0;
            *(uint4*)(abase + aStoreOff + 16)         = H1;
            *(uint4*)(abase + 18432 + aStoreOff)      = L0;
            *(uint4*)(abase + 18432 + aStoreOff + 16) = L1;
            if (kb < 14) {
                const float* xs = xrow + (kb + 2) * 64;
                *(float4*)(xr)      = *(const float4*)(xs);
                *(float4*)(xr + 4)  = *(const float4*)(xs + 4);
                *(float4*)(xr + 8)  = *(const float4*)(xs + 8);
                *(float4*)(xr + 12) = *(const float4*)(xs + 12);
            }
        }
        cp_wait_all();
        __syncthreads();
    }

    float* outs[3] = {g_q, g_k, g_v};
    const int rrow = mw * 16 + (L >> 2);
    const int ccol = (L & 3) * 2;
#pragma unroll
    for (int ln = 0; ln < 12; ln++) {
        const int nc = wsel * 12 + ln;
        const int w = nc >> 3, nt = nc & 7;
        float* obase = outs[w] + (size_t)(m0 + rrow) * H_SZ + nt * 8 + ccol;
        *(float2*)obase              = make_float2(acc[ln][0], acc[ln][1]);
        *(float2*)(obase + 8 * H_SZ) = make_float2(acc[ln][2], acc[ln][3]);
    }
}

// ---------------------------------------------------------------------------
// Kernel 2: causal attention, 512 threads, KV chunk = 128 cols.
// Warp: mw = wid&3 (16-row band), nw = wid>>2 (32 S-cols / 16 V-cols).
// Chunks per (qb, 31-qb) pair = 17 (constant).
// ---------------------------------------------------------------------------
#define AQH 0
#define AQL 9216
#define AKH 18432                        // 128 rows x 144 B
#define AKL 36864
#define AVH 55296                        // 128 rows x 144 B
#define AVL 73728
#define APH 92160                        // 64 rows x 272 B (128 bf16 + pad)
#define APL 109568
#define AEX 126976                       // float2 [64][4]
#define AST 129024                       // s_m[64], s_l[64]
#define ATTN_SMEM (AST + 2 * 64 * 4)     // 129536

__global__ __launch_bounds__(512) void attn_mma_kernel(float* __restrict__ out)
{
    extern __shared__ __align__(128) char smem_raw[];
    const uint32_t sb = smem_u32(smem_raw);
    float2* smEx = (float2*)(smem_raw + AEX);
    float* s_m = (float*)(smem_raw + AST);
    float* s_l = s_m + 64;

    const int b = blockIdx.y;
    const int t = threadIdx.x;
    const int wid = t >> 5, L = t & 31;
    const int mw = wid & 3, nw = wid >> 2;
    // K/V loads: 128 rows, 16 floats/thread
    const int lr  = t >> 2;
    const int lcs = (t & 3) * 16;
    const uint32_t kvOff = lr * 144 + lcs * 2;
    // Q loads: 64 rows, 8 floats/thread
    const int qlr = t >> 3;
    const int qlc = (t & 7) * 8;
    const uint32_t qOff = qlr * 144 + qlc * 2;

    const float* qp = g_q + (size_t)b * T_SZ * H_SZ;
    const float* kp = g_k + (size_t)b * T_SZ * H_SZ;
    const float* vp = g_v + (size_t)b * T_SZ * H_SZ;

    const uint32_t aQ = AQH + (mw * 16 + (L & 15)) * 144 + (L >> 4) * 16;
    const uint32_t aP = APH + (mw * 16 + (L & 15)) * 272 + (L >> 4) * 16;
    const uint32_t bK = AKH + ((L & 7) + ((L >> 4) & 1) * 8 + nw * 32) * 144
                      + ((L >> 3) & 1) * 16;
    const uint32_t vJ = (L & 7) + ((L >> 3) & 1) * 8;
    const uint32_t vC = (nw * 16 + ((L >> 4) & 1) * 8) * 2;

    const int r0 = mw * 16 + (L >> 2);
    const int r1 = r0 + 8;
    const int scol = nw * 32 + (L & 3) * 2;   // S-col base (within 128)
    const int ocol = nw * 16 + (L & 3) * 2;   // O-col base (within 64)

    for (int pass = 0; pass < 2; pass++) {
        const int qb = pass ? 31 - (int)blockIdx.x : (int)blockIdx.x;
        const int q0 = qb * 64;
        const int nch = (qb + 2) >> 1;
        const int gr0 = q0 + r0, gr1 = q0 + r1;

        __syncthreads();   // protect smem/stats from previous pass

        // ---- load + split Q
        {
            const float* qr = qp + (size_t)(q0 + qlr) * H_SZ + qlc;
            float vv[8];
            *(float4*)(vv)     = *(const float4*)(qr);
            *(float4*)(vv + 4) = *(const float4*)(qr + 4);
            uint4 H, Lo;
            cvt8(vv, H, Lo);
            *(uint4*)(smem_raw + AQH + qOff) = H;
            *(uint4*)(smem_raw + AQL + qOff) = Lo;
        }
        if (t < 64) { s_m[t] = -1e30f; s_l[t] = 0.0f; }

        float acc_o[2][4];
#pragma unroll
        for (int i = 0; i < 2; i++)
#pragma unroll
            for (int j = 0; j < 4; j++) acc_o[i][j] = 0.0f;

        // prefetch K chunk 0 (rows lr)
        float kf[16];
        {
            const float* kr = kp + (size_t)lr * H_SZ + lcs;
            *(float4*)(kf)      = *(const float4*)(kr);
            *(float4*)(kf + 4)  = *(const float4*)(kr + 4);
            *(float4*)(kf + 8)  = *(const float4*)(kr + 8);
            *(float4*)(kf + 12) = *(const float4*)(kr + 12);
        }

        for (int ch = 0; ch < nch; ch++) {
            const int k0 = ch * 128;

            // step 1: K split store
            {
                uint4 H, Lo;
                cvt8(kf, H, Lo);
                *(uint4*)(smem_raw + AKH + kvOff) = H;
                *(uint4*)(smem_raw + AKL + kvOff) = Lo;
                cvt8(kf + 8, H, Lo);
                *(uint4*)(smem_raw + AKH + kvOff + 16) = H;
                *(uint4*)(smem_raw + AKL + kvOff + 16) = Lo;
            }
            __syncthreads();   // S1

            // step 3: V load (this chunk) + next-K prefetch
            float vf[16];
            {
                const float* vr = vp + (size_t)(k0 + lr) * H_SZ + lcs;
                *(float4*)(vf)      = *(const float4*)(vr);
                *(float4*)(vf + 4)  = *(const float4*)(vr + 4);
                *(float4*)(vf + 8)  = *(const float4*)(vr + 8);
                *(float4*)(vf + 12) = *(const float4*)(vr + 12);
            }
            if (ch < nch - 1) {
                const float* kr = kp + (size_t)(k0 + 128 + lr) * H_SZ + lcs;
                *(float4*)(kf)      = *(const float4*)(kr);
                *(float4*)(kf + 4)  = *(const float4*)(kr + 4);
                *(float4*)(kf + 8)  = *(const float4*)(kr + 8);
                *(float4*)(kf + 12) = *(const float4*)(kr + 12);
            }

            // step 4: S = Q K^T (3-term), warp tile 16x32
            float s2[4][4];
#pragma unroll
            for (int i = 0; i < 4; i++)
#pragma unroll
                for (int j = 0; j < 4; j++) s2[i][j] = 0.0f;
#pragma unroll
            for (int ks = 0; ks < 4; ks++) {
                const uint32_t kbyte = ks * 32;
                uint32_t qh[4], ql[4];
                ldsm_x4(qh[0], qh[1], qh[2], qh[3], sb + aQ + kbyte);
                ldsm_x4(ql[0], ql[1], ql[2], ql[3], sb + aQ + 9216 + kbyte);
#pragma unroll
                for (int p = 0; p < 2; p++) {
                    const uint32_t bbase = sb + bK + p * 2304 + kbyte;
                    uint32_t bh[4], bl[4];
                    ldsm_x4(bh[0], bh[1], bh[2], bh[3], bbase);
                    ldsm_x4(bl[0], bl[1], bl[2], bl[3], bbase + 18432);
                    mma_bf16(s2[2 * p],     qh, bh[0], bh[1]);
                    mma_bf16(s2[2 * p],     ql, bh[0], bh[1]);
                    mma_bf16(s2[2 * p],     qh, bl[0], bl[1]);
                    mma_bf16(s2[2 * p + 1], qh, bh[2], bh[3]);
                    mma_bf16(s2[2 * p + 1], ql, bh[2], bh[3]);
                    mma_bf16(s2[2 * p + 1], qh, bl[2], bl[3]);
                }
            }

            // step 5: V split store (readers gated by S3)
            {
                uint4 H, Lo;
                cvt8(vf, H, Lo);
                *(uint4*)(smem_raw + AVH + kvOff) = H;
                *(uint4*)(smem_raw + AVL + kvOff) = Lo;
                cvt8(vf + 8, H, Lo);
                *(uint4*)(smem_raw + AVH + kvOff + 16) = H;
                *(uint4*)(smem_raw + AVL + kvOff + 16) = Lo;
            }

            // scale + mask
            const bool last = (ch == nch - 1);
#pragma unroll
            for (int nt = 0; nt < 4; nt++) {
                s2[nt][0] *= 0.03125f; s2[nt][1] *= 0.03125f;
                s2[nt][2] *= 0.03125f; s2[nt][3] *= 0.03125f;
                if (last) {
                    const int gc = k0 + scol + nt * 8;
                    if (gc + 0 > gr0) s2[nt][0] = -1e30f;
                    if (gc + 1 > gr0) s2[nt][1] = -1e30f;
                    if (gc + 0 > gr1) s2[nt][2] = -1e30f;
                    if (gc + 1 > gr1) s2[nt][3] = -1e30f;
                }
            }

            // per-warp partial softmax over 32 cols
            float pm0 = -1e30f, pm1 = -1e30f;
#pragma unroll
            for (int nt = 0; nt < 4; nt++) {
                pm0 = fmaxf(pm0, fmaxf(s2[nt][0], s2[nt][1]));
                pm1 = fmaxf(pm1, fmaxf(s2[nt][2], s2[nt][3]));
            }
            pm0 = qmax(pm0); pm1 = qmax(pm1);
            float ps0 = 0.0f, ps1 = 0.0f;
#pragma unroll
            for (int nt = 0; nt < 4; nt++) {
                s2[nt][0] = __expf(s2[nt][0] - pm0);
                s2[nt][1] = __expf(s2[nt][1] - pm0);
                s2[nt][2] = __expf(s2[nt][2] - pm1);
                s2[nt][3] = __expf(s2[nt][3] - pm1);
                ps0 += s2[nt][0] + s2[nt][1];
                ps1 += s2[nt][2] + s2[nt][3];
            }
            ps0 = qsum(ps0); ps1 = qsum(ps1);
            if ((L & 3) == 0) {
                smEx[r0 * 4 + nw] = make_float2(pm0, ps0);
                smEx[r1 * 4 + nw] = make_float2(pm1, ps1);
            }
            __syncthreads();   // S2

            // combine (all lanes redundantly)
            float mx0, mx1, l0, l1, alpha0, alpha1, f0, f1;
            {
                const float mo0 = s_m[r0], lo0 = s_l[r0];
                const float mo1 = s_m[r1], lo1 = s_l[r1];
                float2 e0[4], e1[4];
#pragma unroll
                for (int i = 0; i < 4; i++) { e0[i] = smEx[r0 * 4 + i]; e1[i] = smEx[r1 * 4 + i]; }
                mx0 = mo0; mx1 = mo1;
#pragma unroll
                for (int i = 0; i < 4; i++) { mx0 = fmaxf(mx0, e0[i].x); mx1 = fmaxf(mx1, e1[i].x); }
                alpha0 = __expf(mo0 - mx0); alpha1 = __expf(mo1 - mx1);
                l0 = lo0 * alpha0; l1 = lo1 * alpha1;
#pragma unroll
                for (int i = 0; i < 4; i++) {
                    l0 += e0[i].y * __expf(e0[i].x - mx0);
                    l1 += e1[i].y * __expf(e1[i].x - mx1);
                }
                f0 = __expf(pm0 - mx0); f1 = __expf(pm1 - mx1);
            }

            // P = e * f -> bf16 hi/lo
#pragma unroll
            for (int nt = 0; nt < 4; nt++) {
                const int c = scol + nt * 8;
                uint32_t hi, lo;
                split2(s2[nt][0] * f0, s2[nt][1] * f0, hi, lo);
                *(uint32_t*)(smem_raw + APH + r0 * 272 + c * 2) = hi;
                *(uint32_t*)(smem_raw + APL + r0 * 272 + c * 2) = lo;
                split2(s2[nt][2] * f1, s2[nt][3] * f1, hi, lo);
                *(uint32_t*)(smem_raw + APH + r1 * 272 + c * 2) = hi;
                *(uint32_t*)(smem_raw + APL + r1 * 272 + c * 2) = lo;
            }
            __syncthreads();   // S3

            if (nw == 0 && (L & 3) == 0) {
                s_m[r0] = mx0; s_l[r0] = l0;
                s_m[r1] = mx1; s_l[r1] = l1;
            }

            // rescale + O += P V (3-term, k = 128 -> 8 steps)
#pragma unroll
            for (int nt = 0; nt < 2; nt++) {
                acc_o[nt][0] *= alpha0; acc_o[nt][1] *= alpha0;
                acc_o[nt][2] *= alpha1; acc_o[nt][3] *= alpha1;
            }
#pragma unroll
            for (int ks = 0; ks < 8; ks++) {
                uint32_t ph[4], pl[4], vh[4], vl[4];
                ldsm_x4(ph[0], ph[1], ph[2], ph[3], sb + aP + ks * 32);
                ldsm_x4(pl[0], pl[1], pl[2], pl[3], sb + aP + 17408 + ks * 32);
                const uint32_t vaddr = sb + AVH + (ks * 16 + vJ) * 144 + vC;
                ldsm_x4_t(vh[0], vh[1], vh[2], vh[3], vaddr);
                ldsm_x4_t(vl[0], vl[1], vl[2], vl[3], vaddr + 18432);
                mma_bf16(acc_o[0], ph, vh[0], vh[1]);
                mma_bf16(acc_o[0], pl, vh[0], vh[1]);
                mma_bf16(acc_o[0], ph, vl[0], vl[1]);
                mma_bf16(acc_o[1], ph, vh[2], vh[3]);
                mma_bf16(acc_o[1], pl, vh[2], vh[3]);
                mma_bf16(acc_o[1], ph, vl[2], vl[3]);
            }
        }

        __syncthreads();   // stats visible for epilogue
        {
            const float inv0 = 1.0f / s_l[r0];
            const float inv1 = 1.0f / s_l[r1];
#pragma unroll
            for (int nt = 0; nt < 2; nt++) {
                const int c = ocol + nt * 8;
                float* ob0 = out + (size_t)(b * T_SZ + q0 + r0) * H_SZ + c;
                float* ob1 = out + (size_t)(b * T_SZ + q0 + r1) * H_SZ + c;
                *(float2*)ob0 = make_float2(acc_o[nt][0] * inv0, acc_o[nt][1] * inv0);
                *(float2*)ob1 = make_float2(acc_o[nt][2] * inv1, acc_o[nt][3] * inv1);
            }
        }
    }
}

// ---------------------------------------------------------------------------
extern "C" void kernel_launch(void* const* d_in, const int* in_sizes, int n_in,
                              void* d_out, int out_size)
{
    const float* x  = (const float*)d_in[0];
    const float* Wq = (const float*)d_in[1];
    const float* Wk = (const float*)d_in[2];
    const float* Wv = (const float*)d_in[3];
    float* out = (float*)d_out;

    cudaFuncSetAttribute(qkv_mma_kernel, cudaFuncAttributeMaxDynamicSharedMemorySize,
                         QKV_SMEM);
    cudaFuncSetAttribute(attn_mma_kernel, cudaFuncAttributeMaxDynamicSharedMemorySize,
                         ATTN_SMEM);

    wsplit_kernel<<<dim3(16, 3), 256>>>(Wq, Wk, Wv);
    qkv_mma_kernel<<<MROWS / 128, 512, QKV_SMEM>>>(x);
    attn_mma_kernel<<<dim3(16, B_SZ), 512, ATTN_SMEM>>>(out);
}

// round 14
// speedup vs baseline: 5.3098x; 1.1544x over previous
#include <cuda_runtime.h>
#include <cuda_bf16.h>
#include <cstdint>
#include <cstddef>

#define B_SZ 8
#define T_SZ 2048
#define C_SZ 1024
#define H_SZ 64
#define MROWS (B_SZ * T_SZ)

typedef unsigned long long u64;

// ---------------- mma.sync helpers ----------------
__device__ __forceinline__ uint32_t smem_u32(const void* p) {
    uint32_t a;
    asm("{ .reg .u64 t; cvta.to.shared.u64 t, %1; cvt.u32.u64 %0, t; }" : "=r"(a) : "l"(p));
    return a;
}
__device__ __forceinline__ void ldsm_x4(uint32_t& r0, uint32_t& r1,
                                        uint32_t& r2, uint32_t& r3, uint32_t addr) {
    asm volatile("ldmatrix.sync.aligned.m8n8.x4.shared.b16 {%0,%1,%2,%3}, [%4];"
                 : "=r"(r0), "=r"(r1), "=r"(r2), "=r"(r3) : "r"(addr));
}
__device__ __forceinline__ void ldsm_x4_t(uint32_t& r0, uint32_t& r1,
                                          uint32_t& r2, uint32_t& r3, uint32_t addr) {
    asm volatile("ldmatrix.sync.aligned.m8n8.x4.trans.shared.b16 {%0,%1,%2,%3}, [%4];"
                 : "=r"(r0), "=r"(r1), "=r"(r2), "=r"(r3) : "r"(addr));
}
__device__ __forceinline__ void mma_bf16(float* c, const uint32_t* a,
                                         uint32_t b0, uint32_t b1) {
    asm volatile(
        "mma.sync.aligned.m16n8k16.row.col.f32.bf16.bf16.f32 "
        "{%0,%1,%2,%3}, {%4,%5,%6,%7}, {%8,%9}, {%0,%1,%2,%3};"
        : "+f"(c[0]), "+f"(c[1]), "+f"(c[2]), "+f"(c[3])
        : "r"(a[0]), "r"(a[1]), "r"(a[2]), "r"(a[3]), "r"(b0), "r"(b1));
}
__device__ __forceinline__ void cvt8(const float* v, uint4& Hu, uint4& Lu) {
    union { __nv_bfloat16 b[8]; uint4 u; } h, l;
#pragma unroll
    for (int i = 0; i < 8; i++) {
        __nv_bfloat16 hb = __float2bfloat16(v[i]);
        h.b[i] = hb;
        l.b[i] = __float2bfloat16(v[i] - __bfloat162float(hb));
    }
    Hu = h.u; Lu = l.u;
}
__device__ __forceinline__ void split2(float a, float b, uint32_t& hi, uint32_t& lo) {
    __nv_bfloat16 ah = __float2bfloat16(a), bh = __float2bfloat16(b);
    __nv_bfloat16 al = __float2bfloat16(a - __bfloat162float(ah));
    __nv_bfloat16 bl = __float2bfloat16(b - __bfloat162float(bh));
    union { __nv_bfloat16 b2[2]; uint32_t u; } H, L;
    H.b2[0] = ah; H.b2[1] = bh; L.b2[0] = al; L.b2[1] = bl;
    hi = H.u; lo = L.u;
}
__device__ __forceinline__ void cp16(uint32_t dst, const void* src) {
    asm volatile("cp.async.ca.shared.global [%0], [%1], 16;" :: "r"(dst), "l"(src));
}
__device__ __forceinline__ void cp_commit() {
    asm volatile("cp.async.commit_group;");
}
__device__ __forceinline__ void cp_wait_all() {
    asm volatile("cp.async.wait_group 0;");
}
__device__ __forceinline__ float qmax(float v) {
    v = fmaxf(v, __shfl_xor_sync(0xffffffffu, v, 1));
    v = fmaxf(v, __shfl_xor_sync(0xffffffffu, v, 2));
    return v;
}
__device__ __forceinline__ float qsum(float v) {
    v += __shfl_xor_sync(0xffffffffu, v, 1);
    v += __shfl_xor_sync(0xffffffffu, v, 2);
    return v;
}

// ---------------- scratch: bf16 hi/lo split q/k/v ----------------
__device__ __nv_bfloat16 g_qh[MROWS * H_SZ];
__device__ __nv_bfloat16 g_ql[MROWS * H_SZ];
__device__ __nv_bfloat16 g_kh[MROWS * H_SZ];
__device__ __nv_bfloat16 g_kl[MROWS * H_SZ];
__device__ __nv_bfloat16 g_vh[MROWS * H_SZ];
__device__ __nv_bfloat16 g_vl[MROWS * H_SZ];
__device__ __nv_bfloat16 g_wT_hi[3][64][C_SZ];
__device__ __nv_bfloat16 g_wT_lo[3][64][C_SZ];

// ---------------------------------------------------------------------------
// Kernel 0: transpose + bf16 hi/lo split of the three weight matrices.
// ---------------------------------------------------------------------------
__global__ __launch_bounds__(256) void wsplit_kernel(
    const float* __restrict__ Wq, const float* __restrict__ Wk,
    const float* __restrict__ Wv)
{
    __shared__ float tile[64][65];
    const int w  = blockIdx.y;
    const int k0 = blockIdx.x * 64;
    const float* W = (w == 0) ? Wq : (w == 1) ? Wk : Wv;
    const int t = threadIdx.x;
    {
        int r = t >> 2, cs = (t & 3) * 16;
#pragma unroll
        for (int j = 0; j < 4; j++) {
            float4 v = *(const float4*)(W + (size_t)(k0 + r) * 64 + cs + j * 4);
            tile[r][cs + j * 4 + 0] = v.x; tile[r][cs + j * 4 + 1] = v.y;
            tile[r][cs + j * 4 + 2] = v.z; tile[r][cs + j * 4 + 3] = v.w;
        }
    }
    __syncthreads();
    {
        int n = t >> 2, ks = (t & 3) * 16;
        float vv[16];
#pragma unroll
        for (int i = 0; i < 16; i++) vv[i] = tile[ks + i][n];
        uint4 H0, L0, H1, L1;
        cvt8(vv, H0, L0); cvt8(vv + 8, H1, L1);
        *(uint4*)&g_wT_hi[w][n][k0 + ks]     = H0;
        *(uint4*)&g_wT_hi[w][n][k0 + ks + 8] = H1;
        *(uint4*)&g_wT_lo[w][n][k0 + ks]     = L0;
        *(uint4*)&g_wT_lo[w][n][k0 + ks + 8] = L1;
    }
}

// ---------------------------------------------------------------------------
// Kernel 1: QKV via mma.sync, cp.async double-buffered.
// Epilogue now writes split bf16 hi/lo directly (consumed by attn).
// ---------------------------------------------------------------------------
#define QKV_B_OFF 73728
#define QKV_SMEM  (QKV_B_OFF + 2 * 6 * 9216)

__global__ __launch_bounds__(512) void qkv_mma_kernel(const float* __restrict__ x)
{
    extern __shared__ __align__(128) char smem_raw[];
    const uint32_t sb = smem_u32(smem_raw);
    const int t = threadIdx.x;
    const int wid = t >> 5, L = t & 31;
    const int mw = wid & 7, wsel = wid >> 3;
    const int m0 = blockIdx.x * 128;

    const uint32_t aRowOff = (mw * 16 + (L & 15)) * 144 + (L >> 4) * 16;
    const uint32_t bLaneOff = ((L & 7) + ((L >> 4) & 1) * 8) * 144 + ((L >> 3) & 1) * 16;

    const int ar   = t >> 2;
    const int aseg = (t & 3) * 16;
    const float* xrow = x + (size_t)(m0 + ar) * C_SZ + aseg;
    const uint32_t aStoreOff = ar * 144 + aseg * 2;

    const __nv_bfloat16* bsrc[6] = {
        &g_wT_hi[0][0][0], &g_wT_lo[0][0][0],
        &g_wT_hi[1][0][0], &g_wT_lo[1][0][0],
        &g_wT_hi[2][0][0], &g_wT_lo[2][0][0] };
    int cbuf[6], cn[6], ckc[6];
#pragma unroll
    for (int i = 0; i < 6; i++) {
        const int idx = t + i * 512;
        cbuf[i] = idx >> 9;
        cn[i]   = (idx & 511) >> 3;
        ckc[i]  = idx & 7;
    }

    float acc[12][4];
#pragma unroll
    for (int i = 0; i < 12; i++)
#pragma unroll
        for (int j = 0; j < 4; j++) acc[i][j] = 0.0f;

    float xr[16];
    *(float4*)(xr)      = *(const float4*)(xrow);
    *(float4*)(xr + 4)  = *(const float4*)(xrow + 4);
    *(float4*)(xr + 8)  = *(const float4*)(xrow + 8);
    *(float4*)(xr + 12) = *(const float4*)(xrow + 12);
#pragma unroll
    for (int i = 0; i < 6; i++)
        cp16(sb + QKV_B_OFF + cbuf[i] * 9216 + cn[i] * 144 + ckc[i] * 16,
             bsrc[cbuf[i]] + (size_t)cn[i] * C_SZ + ckc[i] * 8);
    cp_commit();
    {
        uint4 H0, L0, H1, L1;
        cvt8(xr, H0, L0); cvt8(xr + 8, H1, L1);
        *(uint4*)(smem_raw + aStoreOff)              = H0;
        *(uint4*)(smem_raw + aStoreOff + 16)         = H1;
        *(uint4*)(smem_raw + 18432 + aStoreOff)      = L0;
        *(uint4*)(smem_raw + 18432 + aStoreOff + 16) = L1;
    }
    *(float4*)(xr)      = *(const float4*)(xrow + 64);
    *(float4*)(xr + 4)  = *(const float4*)(xrow + 68);
    *(float4*)(xr + 8)  = *(const float4*)(xrow + 72);
    *(float4*)(xr + 12) = *(const float4*)(xrow + 76);
    cp_wait_all();
    __syncthreads();

    for (int kb = 0; kb < 16; kb++) {
        const int cur = kb & 1, nxt = cur ^ 1;
        if (kb < 15) {
#pragma unroll
            for (int i = 0; i < 6; i++)
                cp16(sb + QKV_B_OFF + nxt * 55296 + cbuf[i] * 9216 + cn[i] * 144 + ckc[i] * 16,
                     bsrc[cbuf[i]] + (size_t)cn[i] * C_SZ + (kb + 1) * 64 + ckc[i] * 8);
            cp_commit();
        }

        const uint32_t aHi = sb + cur * 36864 + aRowOff;
        const uint32_t aLo = aHi + 18432;
        const uint32_t bB  = sb + QKV_B_OFF + cur * 55296 + bLaneOff;
#pragma unroll
        for (int ks = 0; ks < 4; ks++) {
            const uint32_t kbyte = ks * 32;
            uint32_t ah[4], al[4];
            ldsm_x4(ah[0], ah[1], ah[2], ah[3], aHi + kbyte);
            ldsm_x4(al[0], al[1], al[2], al[3], aLo + kbyte);
#pragma unroll
            for (int p = 0; p < 6; p++) {
                const int nc = wsel * 12 + 2 * p;
                const int w = nc >> 3, nt = nc & 7;
                const uint32_t bbase = bB + (w * 2) * 9216 + nt * 1152 + kbyte;
                uint32_t bh[4], bl[4];
                ldsm_x4(bh[0], bh[1], bh[2], bh[3], bbase);
                ldsm_x4(bl[0], bl[1], bl[2], bl[3], bbase + 9216);
                mma_bf16(acc[2 * p],     ah, bh[0], bh[1]);
                mma_bf16(acc[2 * p],     al, bh[0], bh[1]);
                mma_bf16(acc[2 * p],     ah, bl[0], bl[1]);
                mma_bf16(acc[2 * p + 1], ah, bh[2], bh[3]);
                mma_bf16(acc[2 * p + 1], al, bh[2], bh[3]);
                mma_bf16(acc[2 * p + 1], ah, bl[2], bl[3]);
            }
        }

        if (kb < 15) {
            uint4 H0, L0, H1, L1;
            cvt8(xr, H0, L0); cvt8(xr + 8, H1, L1);
            char* abase = smem_raw + nxt * 36864;
            *(uint4*)(abase + aStoreOff)              = H0;
            *(uint4*)(abase + aStoreOff + 16)         = H1;
            *(uint4*)(abase + 18432 + aStoreOff)      = L0;
            *(uint4*)(abase + 18432 + aStoreOff + 16) = L1;
            if (kb < 14) {
                const float* xs = xrow + (kb + 2) * 64;
                *(float4*)(xr)      = *(const float4*)(xs);
                *(float4*)(xr + 4)  = *(const float4*)(xs + 4);
                *(float4*)(xr + 8)  = *(const float4*)(xs + 8);
                *(float4*)(xr + 12) = *(const float4*)(xs + 12);
            }
        }
        cp_wait_all();
        __syncthreads();
    }

    // ---- epilogue: write split bf16 hi/lo
    __nv_bfloat16* outsH[3] = {g_qh, g_kh, g_vh};
    __nv_bfloat16* outsL[3] = {g_ql, g_kl, g_vl};
    const int rrow = mw * 16 + (L >> 2);
    const int ccol = (L & 3) * 2;
#pragma unroll
    for (int ln = 0; ln < 12; ln++) {
        const int nc = wsel * 12 + ln;
        const int w = nc >> 3, nt = nc & 7;
        const size_t o0 = (size_t)(m0 + rrow) * H_SZ + nt * 8 + ccol;
        const size_t o1 = o0 + 8 * H_SZ;
        uint32_t hi, lo;
        split2(acc[ln][0], acc[ln][1], hi, lo);
        *(uint32_t*)&outsH[w][o0] = hi;
        *(uint32_t*)&outsL[w][o0] = lo;
        split2(acc[ln][2], acc[ln][3], hi, lo);
        *(uint32_t*)&outsH[w][o1] = hi;
        *(uint32_t*)&outsL[w][o1] = lo;
    }
}

// ---------------------------------------------------------------------------
// Kernel 2: causal attention.  512 threads, KV chunk 128, cp.async K/V
// double-buffered, per-warp softmax (no exchange), P in registers,
// split-k merge across nw groups at pass end.
// ---------------------------------------------------------------------------
#define AQH 0
#define AQL 9216
#define KBUF(b) (18432 + (b) * 36864)        // hi; lo = +18432
#define VBUF(b) (92160 + (b) * 36864)
#define MRG 18432                            // float [64][68], aliases K bufs
#define SSTAT 165888                         // float2 [64][4]
#define ATTN_SMEM (SSTAT + 2048)             // 167936

__global__ __launch_bounds__(512) void attn_mma_kernel(float* __restrict__ out)
{
    extern __shared__ __align__(128) char smem_raw[];
    const uint32_t sb = smem_u32(smem_raw);
    float* smMrg = (float*)(smem_raw + MRG);
    float2* smSt = (float2*)(smem_raw + SSTAT);

    const int b = blockIdx.y;
    const int t = threadIdx.x;
    const int wid = t >> 5, L = t & 31;
    const int mw = wid & 3, nw = wid >> 2;

    // copy indices: Q (1 seg/thread), K/V (2 segs/thread each hi+lo)
    const int qrow = t >> 3, qseg = t & 7;

    const __nv_bfloat16* qhp = g_qh + (size_t)b * T_SZ * H_SZ;
    const __nv_bfloat16* qlp = g_ql + (size_t)b * T_SZ * H_SZ;
    const __nv_bfloat16* khp = g_kh + (size_t)b * T_SZ * H_SZ;
    const __nv_bfloat16* klp = g_kl + (size_t)b * T_SZ * H_SZ;
    const __nv_bfloat16* vhp = g_vh + (size_t)b * T_SZ * H_SZ;
    const __nv_bfloat16* vlp = g_vl + (size_t)b * T_SZ * H_SZ;

    const uint32_t aQ = AQH + (mw * 16 + (L & 15)) * 144 + (L >> 4) * 16;
    const uint32_t bKoff = ((L & 7) + ((L >> 4) & 1) * 8 + nw * 32) * 144
                         + ((L >> 3) & 1) * 16;
    const uint32_t vJ = (L & 7) + ((L >> 3) & 1) * 8;
    const uint32_t vColB = ((L >> 4) & 1) * 16;

    const int r0 = mw * 16 + (L >> 2);
    const int r1 = r0 + 8;
    const int scol = nw * 32 + (L & 3) * 2;   // this warp's S col base

    for (int pass = 0; pass < 2; pass++) {
        const int qb = pass ? 31 - (int)blockIdx.x : (int)blockIdx.x;
        const int q0 = qb * 64;
        const int nch = (qb + 2) >> 1;
        const int gr0 = q0 + r0, gr1 = q0 + r1;

        __syncthreads();   // protect smem (merge/stat/K/V) from previous pass

        // ---- prologue copies: Q + KV chunk 0 -> buf 0
        cp16(sb + AQH + qrow * 144 + qseg * 16, qhp + (size_t)(q0 + qrow) * 64 + qseg * 8);
        cp16(sb + AQL + qrow * 144 + qseg * 16, qlp + (size_t)(q0 + qrow) * 64 + qseg * 8);
#pragma unroll
        for (int i = 0; i < 2; i++) {
            const int idx = t + i * 512;
            const int row = idx >> 3, seg = idx & 7;
            const uint32_t so = row * 144 + seg * 16;
            const size_t go = (size_t)row * 64 + seg * 8;
            cp16(sb + KBUF(0) + so,         khp + go);
            cp16(sb + KBUF(0) + 18432 + so, klp + go);
            cp16(sb + VBUF(0) + so,         vhp + go);
            cp16(sb + VBUF(0) + 18432 + so, vlp + go);
        }
        cp_commit();

        // per-warp softmax state + O partials
        float m_w0 = -1e30f, m_w1 = -1e30f, l_w0 = 0.0f, l_w1 = 0.0f;
        float acc_o[8][4];
#pragma unroll
        for (int i = 0; i < 8; i++)
#pragma unroll
            for (int j = 0; j < 4; j++) acc_o[i][j] = 0.0f;

        for (int ch = 0; ch < nch; ch++) {
            const int cur = ch & 1;
            cp_wait_all();
            __syncthreads();   // S1: KV cur (+Q on ch 0) visible; prev readers done

            // issue next chunk copies (overlap with compute)
            if (ch + 1 < nch) {
                const int nk0 = (ch + 1) * 128;
                const int nxt = cur ^ 1;
#pragma unroll
                for (int i = 0; i < 2; i++) {
                    const int idx = t + i * 512;
                    const int row = idx >> 3, seg = idx & 7;
                    const uint32_t so = row * 144 + seg * 16;
                    const size_t go = (size_t)(nk0 + row) * 64 + seg * 8;
                    cp16(sb + KBUF(nxt) + so,         khp + go);
                    cp16(sb + KBUF(nxt) + 18432 + so, klp + go);
                    cp16(sb + VBUF(nxt) + so,         vhp + go);
                    cp16(sb + VBUF(nxt) + 18432 + so, vlp + go);
                }
                cp_commit();
            }

            // ---- S = Q K^T (3-term), warp tile 16x32
            float s2[4][4];
#pragma unroll
            for (int i = 0; i < 4; i++)
#pragma unroll
                for (int j = 0; j < 4; j++) s2[i][j] = 0.0f;
            const uint32_t bK = sb + KBUF(cur) + bKoff;
#pragma unroll
            for (int ks = 0; ks < 4; ks++) {
                const uint32_t kbyte = ks * 32;
                uint32_t qh[4], ql[4];
                ldsm_x4(qh[0], qh[1], qh[2], qh[3], sb + aQ + kbyte);
                ldsm_x4(ql[0], ql[1], ql[2], ql[3], sb + aQ + 9216 + kbyte);
#pragma unroll
                for (int p = 0; p < 2; p++) {
                    const uint32_t bbase = bK + p * 2304 + kbyte;
                    uint32_t bh[4], bl[4];
                    ldsm_x4(bh[0], bh[1], bh[2], bh[3], bbase);
                    ldsm_x4(bl[0], bl[1], bl[2], bl[3], bbase + 18432);
                    mma_bf16(s2[2 * p],     qh, bh[0], bh[1]);
                    mma_bf16(s2[2 * p],     ql, bh[0], bh[1]);
                    mma_bf16(s2[2 * p],     qh, bl[0], bl[1]);
                    mma_bf16(s2[2 * p + 1], qh, bh[2], bh[3]);
                    mma_bf16(s2[2 * p + 1], ql, bh[2], bh[3]);
                    mma_bf16(s2[2 * p + 1], qh, bl[2], bl[3]);
                }
            }

            // ---- scale + causal mask
            const int k0 = ch * 128;
            const bool last = (ch == nch - 1);
#pragma unroll
            for (int nt = 0; nt < 4; nt++) {
                s2[nt][0] *= 0.03125f; s2[nt][1] *= 0.03125f;
                s2[nt][2] *= 0.03125f; s2[nt][3] *= 0.03125f;
                if (last) {
                    const int gc = k0 + scol + nt * 8;
                    if (gc + 0 > gr0) s2[nt][0] = -1e30f;
                    if (gc + 1 > gr0) s2[nt][1] = -1e30f;
                    if (gc + 0 > gr1) s2[nt][2] = -1e30f;
                    if (gc + 1 > gr1) s2[nt][3] = -1e30f;
                }
            }

            // ---- per-warp online softmax (32-col slice, quad reduce only)
            float pm0 = -1e30f, pm1 = -1e30f;
#pragma unroll
            for (int nt = 0; nt < 4; nt++) {
                pm0 = fmaxf(pm0, fmaxf(s2[nt][0], s2[nt][1]));
                pm1 = fmaxf(pm1, fmaxf(s2[nt][2], s2[nt][3]));
            }
            pm0 = qmax(pm0); pm1 = qmax(pm1);
            const float mn0 = fmaxf(m_w0, pm0), mn1 = fmaxf(m_w1, pm1);
            const float alpha0 = __expf(m_w0 - mn0), alpha1 = __expf(m_w1 - mn1);
            float ps0 = 0.0f, ps1 = 0.0f;
#pragma unroll
            for (int nt = 0; nt < 4; nt++) {
                s2[nt][0] = __expf(s2[nt][0] - mn0);
                s2[nt][1] = __expf(s2[nt][1] - mn0);
                s2[nt][2] = __expf(s2[nt][2] - mn1);
                s2[nt][3] = __expf(s2[nt][3] - mn1);
                ps0 += s2[nt][0] + s2[nt][1];
                ps1 += s2[nt][2] + s2[nt][3];
            }
            l_w0 = l_w0 * alpha0 + qsum(ps0);
            l_w1 = l_w1 * alpha1 + qsum(ps1);
            m_w0 = mn0; m_w1 = mn1;

            // ---- rescale O partials
#pragma unroll
            for (int i = 0; i < 8; i++) {
                acc_o[i][0] *= alpha0; acc_o[i][1] *= alpha0;
                acc_o[i][2] *= alpha1; acc_o[i][3] *= alpha1;
            }

            // ---- P (C-frag) -> A-frags in registers, then O += P V
#pragma unroll
            for (int ks = 0; ks < 2; ks++) {
                uint32_t ph[4], pl[4];
                split2(s2[2 * ks][0],     s2[2 * ks][1],     ph[0], pl[0]);
                split2(s2[2 * ks][2],     s2[2 * ks][3],     ph[1], pl[1]);
                split2(s2[2 * ks + 1][0], s2[2 * ks + 1][1], ph[2], pl[2]);
                split2(s2[2 * ks + 1][2], s2[2 * ks + 1][3], ph[3], pl[3]);
                const uint32_t vrow = sb + VBUF(cur)
                                    + (nw * 32 + ks * 16 + vJ) * 144 + vColB;
#pragma unroll
                for (int vn = 0; vn < 4; vn++) {
                    uint32_t vh[4], vl[4];
                    ldsm_x4_t(vh[0], vh[1], vh[2], vh[3], vrow + vn * 32);
                    ldsm_x4_t(vl[0], vl[1], vl[2], vl[3], vrow + vn * 32 + 18432);
                    mma_bf16(acc_o[2 * vn],     ph, vh[0], vh[1]);
                    mma_bf16(acc_o[2 * vn],     pl, vh[0], vh[1]);
                    mma_bf16(acc_o[2 * vn],     ph, vl[0], vl[1]);
                    mma_bf16(acc_o[2 * vn + 1], ph, vh[2], vh[3]);
                    mma_bf16(acc_o[2 * vn + 1], pl, vh[2], vh[3]);
                    mma_bf16(acc_o[2 * vn + 1], ph, vl[2], vl[3]);
                }
            }
        }

        // ---- split-k merge across the 4 nw groups
        if ((L & 3) == 0) {
            smSt[r0 * 4 + nw] = make_float2(m_w0, l_w0);
            smSt[r1 * 4 + nw] = make_float2(m_w1, l_w1);
        }
        __syncthreads();   // stats visible; all warps done with K/V (alias safe)
        float f0, f1;
        {
            float2 e0[4], e1[4];
#pragma unroll
            for (int i = 0; i < 4; i++) { e0[i] = smSt[r0 * 4 + i]; e1[i] = smSt[r1 * 4 + i]; }
            float M0 = e0[0].x, M1 = e1[0].x;
#pragma unroll
            for (int i = 1; i < 4; i++) { M0 = fmaxf(M0, e0[i].x); M1 = fmaxf(M1, e1[i].x); }
            float Lt0 = 0.0f, Lt1 = 0.0f;
#pragma unroll
            for (int i = 0; i < 4; i++) {
                Lt0 += e0[i].y * __expf(e0[i].x - M0);
                Lt1 += e1[i].y * __expf(e1[i].x - M1);
            }
            f0 = __expf(m_w0 - M0) / Lt0;
            f1 = __expf(m_w1 - M1) / Lt1;
        }
#pragma unroll
        for (int i = 0; i < 8; i++) {
            acc_o[i][0] *= f0; acc_o[i][1] *= f0;
            acc_o[i][2] *= f1; acc_o[i][3] *= f1;
        }

        const int mc = (L & 3) * 2;
        if (nw == 0) {
#pragma unroll
            for (int vn = 0; vn < 8; vn++) {
                *(float2*)&smMrg[r0 * 68 + vn * 8 + mc] = make_float2(acc_o[vn][0], acc_o[vn][1]);
                *(float2*)&smMrg[r1 * 68 + vn * 8 + mc] = make_float2(acc_o[vn][2], acc_o[vn][3]);
            }
        }
        __syncthreads();
        if (nw == 1) {
#pragma unroll
            for (int vn = 0; vn < 8; vn++) {
                float2 a = *(float2*)&smMrg[r0 * 68 + vn * 8 + mc];
                *(float2*)&smMrg[r0 * 68 + vn * 8 + mc] = make_float2(a.x + acc_o[vn][0], a.y + acc_o[vn][1]);
                float2 c = *(float2*)&smMrg[r1 * 68 + vn * 8 + mc];
                *(float2*)&smMrg[r1 * 68 + vn * 8 + mc] = make_float2(c.x + acc_o[vn][2], c.y + acc_o[vn][3]);
            }
        }
        __syncthreads();
        if (nw == 2) {
#pragma unroll
            for (int vn = 0; vn < 8; vn++) {
                float2 a = *(float2*)&smMrg[r0 * 68 + vn * 8 + mc];
                *(float2*)&smMrg[r0 * 68 + vn * 8 + mc] = make_float2(a.x + acc_o[vn][0], a.y + acc_o[vn][1]);
                float2 c = *(float2*)&smMrg[r1 * 68 + vn * 8 + mc];
                *(float2*)&smMrg[r1 * 68 + vn * 8 + mc] = make_float2(c.x + acc_o[vn][2], c.y + acc_o[vn][3]);
            }
        }
        __syncthreads();
        if (nw == 3) {
#pragma unroll
            for (int vn = 0; vn < 8; vn++) {
                float2 a = *(float2*)&smMrg[r0 * 68 + vn * 8 + mc];
                float2 c = *(float2*)&smMrg[r1 * 68 + vn * 8 + mc];
                *(float2*)(out + (size_t)(b * T_SZ + gr0) * H_SZ + vn * 8 + mc)
                    = make_float2(a.x + acc_o[vn][0], a.y + acc_o[vn][1]);
                *(float2*)(out + (size_t)(b * T_SZ + gr1) * H_SZ + vn * 8 + mc)
                    = make_float2(c.x + acc_o[vn][2], c.y + acc_o[vn][3]);
            }
        }
    }
}

// ---------------------------------------------------------------------------
extern "C" void kernel_launch(void* const* d_in, const int* in_sizes, int n_in,
                              void* d_out, int out_size)
{
    const float* x  = (const float*)d_in[0];
    const float* Wq = (const float*)d_in[1];
    const float* Wk = (const float*)d_in[2];
    const float* Wv = (const float*)d_in[3];
    float* out = (float*)d_out;

    cudaFuncSetAttribute(qkv_mma_kernel, cudaFuncAttributeMaxDynamicSharedMemorySize,
                         QKV_SMEM);
    cudaFuncSetAttribute(attn_mma_kernel, cudaFuncAttributeMaxDynamicSharedMemorySize,
                         ATTN_SMEM);

    wsplit_kernel<<<dim3(16, 3), 256>>>(Wq, Wk, Wv);
    qkv_mma_kernel<<<MROWS / 128, 512, QKV_SMEM>>>(x);
    attn_mma_kernel<<<dim3(16, B_SZ), 512, ATTN_SMEM>>>(out);
}

// round 17
// speedup vs baseline: 5.4097x; 1.0188x over previous
#include <cuda_runtime.h>
#include <cuda_bf16.h>
#include <cstdint>
#include <cstddef>

#define B_SZ 8
#define T_SZ 2048
#define C_SZ 1024
#define H_SZ 64
#define MROWS (B_SZ * T_SZ)

typedef unsigned long long u64;

// ---------------- mma.sync helpers ----------------
__device__ __forceinline__ uint32_t smem_u32(const void* p) {
    uint32_t a;
    asm("{ .reg .u64 t; cvta.to.shared.u64 t, %1; cvt.u32.u64 %0, t; }" : "=r"(a) : "l"(p));
    return a;
}
__device__ __forceinline__ void ldsm_x4(uint32_t& r0, uint32_t& r1,
                                        uint32_t& r2, uint32_t& r3, uint32_t addr) {
    asm volatile("ldmatrix.sync.aligned.m8n8.x4.shared.b16 {%0,%1,%2,%3}, [%4];"
                 : "=r"(r0), "=r"(r1), "=r"(r2), "=r"(r3) : "r"(addr));
}
__device__ __forceinline__ void ldsm_x4_t(uint32_t& r0, uint32_t& r1,
                                          uint32_t& r2, uint32_t& r3, uint32_t addr) {
    asm volatile("ldmatrix.sync.aligned.m8n8.x4.trans.shared.b16 {%0,%1,%2,%3}, [%4];"
                 : "=r"(r0), "=r"(r1), "=r"(r2), "=r"(r3) : "r"(addr));
}
__device__ __forceinline__ void mma_bf16(float* c, const uint32_t* a,
                                         uint32_t b0, uint32_t b1) {
    asm volatile(
        "mma.sync.aligned.m16n8k16.row.col.f32.bf16.bf16.f32 "
        "{%0,%1,%2,%3}, {%4,%5,%6,%7}, {%8,%9}, {%0,%1,%2,%3};"
        : "+f"(c[0]), "+f"(c[1]), "+f"(c[2]), "+f"(c[3])
        : "r"(a[0]), "r"(a[1]), "r"(a[2]), "r"(a[3]), "r"(b0), "r"(b1));
}
// Packed hi/lo split: one cvt.rn.bf16x2 per half (identical rn rounding).
__device__ __forceinline__ void split2(float a, float b, uint32_t& hi, uint32_t& lo) {
    asm("cvt.rn.bf16x2.f32 %0, %1, %2;" : "=r"(hi) : "f"(b), "f"(a));
    float ah = __uint_as_float(hi << 16);
    float bh = __uint_as_float(hi & 0xFFFF0000u);
    float al = a - ah, bl = b - bh;
    asm("cvt.rn.bf16x2.f32 %0, %1, %2;" : "=r"(lo) : "f"(bl), "f"(al));
}
__device__ __forceinline__ void cvt8(const float* v, uint4& Hu, uint4& Lu) {
    uint32_t* H = (uint32_t*)&Hu;
    uint32_t* L = (uint32_t*)&Lu;
#pragma unroll
    for (int i = 0; i < 4; i++)
        split2(v[2 * i], v[2 * i + 1], H[i], L[i]);
}
__device__ __forceinline__ void cp16(uint32_t dst, const void* src) {
    asm volatile("cp.async.ca.shared.global [%0], [%1], 16;" :: "r"(dst), "l"(src));
}
__device__ __forceinline__ void cp_commit() {
    asm volatile("cp.async.commit_group;");
}
__device__ __forceinline__ void cp_wait_all() {
    asm volatile("cp.async.wait_group 0;");
}
__device__ __forceinline__ float qmax(float v) {
    v = fmaxf(v, __shfl_xor_sync(0xffffffffu, v, 1));
    v = fmaxf(v, __shfl_xor_sync(0xffffffffu, v, 2));
    return v;
}
__device__ __forceinline__ float qsum(float v) {
    v += __shfl_xor_sync(0xffffffffu, v, 1);
    v += __shfl_xor_sync(0xffffffffu, v, 2);
    return v;
}

// ---------------- scratch: bf16 hi/lo split q/k/v ----------------
__device__ __nv_bfloat16 g_qh[MROWS * H_SZ];
__device__ __nv_bfloat16 g_ql[MROWS * H_SZ];
__device__ __nv_bfloat16 g_kh[MROWS * H_SZ];
__device__ __nv_bfloat16 g_kl[MROWS * H_SZ];
__device__ __nv_bfloat16 g_vh[MROWS * H_SZ];
__device__ __nv_bfloat16 g_vl[MROWS * H_SZ];
__device__ __nv_bfloat16 g_wT_hi[3][64][C_SZ];
__device__ __nv_bfloat16 g_wT_lo[3][64][C_SZ];

// ---------------------------------------------------------------------------
// Kernel 0: transpose + bf16 hi/lo split of the three weight matrices.
// ---------------------------------------------------------------------------
__global__ __launch_bounds__(256) void wsplit_kernel(
    const float* __restrict__ Wq, const float* __restrict__ Wk,
    const float* __restrict__ Wv)
{
    __shared__ float tile[64][65];
    const int w  = blockIdx.y;
    const int k0 = blockIdx.x * 64;
    const float* W = (w == 0) ? Wq : (w == 1) ? Wk : Wv;
    const int t = threadIdx.x;
    {
        int r = t >> 2, cs = (t & 3) * 16;
#pragma unroll
        for (int j = 0; j < 4; j++) {
            float4 v = *(const float4*)(W + (size_t)(k0 + r) * 64 + cs + j * 4);
            tile[r][cs + j * 4 + 0] = v.x; tile[r][cs + j * 4 + 1] = v.y;
            tile[r][cs + j * 4 + 2] = v.z; tile[r][cs + j * 4 + 3] = v.w;
        }
    }
    __syncthreads();
    {
        int n = t >> 2, ks = (t & 3) * 16;
        float vv[16];
#pragma unroll
        for (int i = 0; i < 16; i++) vv[i] = tile[ks + i][n];
        uint4 H0, L0, H1, L1;
        cvt8(vv, H0, L0); cvt8(vv + 8, H1, L1);
        *(uint4*)&g_wT_hi[w][n][k0 + ks]     = H0;
        *(uint4*)&g_wT_hi[w][n][k0 + ks + 8] = H1;
        *(uint4*)&g_wT_lo[w][n][k0 + ks]     = L0;
        *(uint4*)&g_wT_lo[w][n][k0 + ks + 8] = L1;
    }
}

// ---------------------------------------------------------------------------
// Kernel 1: QKV via mma.sync, cp.async double-buffered.
// Epilogue writes split bf16 hi/lo directly (consumed by attn).
// ---------------------------------------------------------------------------
#define QKV_B_OFF 73728
#define QKV_SMEM  (QKV_B_OFF + 2 * 6 * 9216)

__global__ __launch_bounds__(512) void qkv_mma_kernel(const float* __restrict__ x)
{
    extern __shared__ __align__(128) char smem_raw[];
    const uint32_t sb = smem_u32(smem_raw);
    const int t = threadIdx.x;
    const int wid = t >> 5, L = t & 31;
    const int mw = wid & 7, wsel = wid >> 3;
    const int m0 = blockIdx.x * 128;

    const uint32_t aRowOff = (mw * 16 + (L & 15)) * 144 + (L >> 4) * 16;
    const uint32_t bLaneOff = ((L & 7) + ((L >> 4) & 1) * 8) * 144 + ((L >> 3) & 1) * 16;

    const int ar   = t >> 2;
    const int aseg = (t & 3) * 16;
    const float* xrow = x + (size_t)(m0 + ar) * C_SZ + aseg;
    const uint32_t aStoreOff = ar * 144 + aseg * 2;

    const __nv_bfloat16* bsrc[6] = {
        &g_wT_hi[0][0][0], &g_wT_lo[0][0][0],
        &g_wT_hi[1][0][0], &g_wT_lo[1][0][0],
        &g_wT_hi[2][0][0], &g_wT_lo[2][0][0] };
    int cbuf[6], cn[6], ckc[6];
#pragma unroll
    for (int i = 0; i < 6; i++) {
        const int idx = t + i * 512;
        cbuf[i] = idx >> 9;
        cn[i]   = (idx & 511) >> 3;
        ckc[i]  = idx & 7;
    }

    float acc[12][4];
#pragma unroll
    for (int i = 0; i < 12; i++)
#pragma unroll
        for (int j = 0; j < 4; j++) acc[i][j] = 0.0f;

    float xr[16];
    *(float4*)(xr)      = *(const float4*)(xrow);
    *(float4*)(xr + 4)  = *(const float4*)(xrow + 4);
    *(float4*)(xr + 8)  = *(const float4*)(xrow + 8);
    *(float4*)(xr + 12) = *(const float4*)(xrow + 12);
#pragma unroll
    for (int i = 0; i < 6; i++)
        cp16(sb + QKV_B_OFF + cbuf[i] * 9216 + cn[i] * 144 + ckc[i] * 16,
             bsrc[cbuf[i]] + (size_t)cn[i] * C_SZ + ckc[i] * 8);
    cp_commit();
    {
        uint4 H0, L0, H1, L1;
        cvt8(xr, H0, L0); cvt8(xr + 8, H1, L1);
        *(uint4*)(smem_raw + aStoreOff)              = H0;
        *(uint4*)(smem_raw + aStoreOff + 16)         = H1;
        *(uint4*)(smem_raw + 18432 + aStoreOff)      = L0;
        *(uint4*)(smem_raw + 18432 + aStoreOff + 16) = L1;
    }
    *(float4*)(xr)      = *(const float4*)(xrow + 64);
    *(float4*)(xr + 4)  = *(const float4*)(xrow + 68);
    *(float4*)(xr + 8)  = *(const float4*)(xrow + 72);
    *(float4*)(xr + 12) = *(const float4*)(xrow + 76);
    cp_wait_all();
    __syncthreads();

    for (int kb = 0; kb < 16; kb++) {
        const int cur = kb & 1, nxt = cur ^ 1;
        if (kb < 15) {
#pragma unroll
            for (int i = 0; i < 6; i++)
                cp16(sb + QKV_B_OFF + nxt * 55296 + cbuf[i] * 9216 + cn[i] * 144 + ckc[i] * 16,
                     bsrc[cbuf[i]] + (size_t)cn[i] * C_SZ + (kb + 1) * 64 + ckc[i] * 8);
            cp_commit();
        }

        const uint32_t aHi = sb + cur * 36864 + aRowOff;
        const uint32_t aLo = aHi + 18432;
        const uint32_t bB  = sb + QKV_B_OFF + cur * 55296 + bLaneOff;
#pragma unroll
        for (int ks = 0; ks < 4; ks++) {
            const uint32_t kbyte = ks * 32;
            uint32_t ah[4], al[4];
            ldsm_x4(ah[0], ah[1], ah[2], ah[3], aHi + kbyte);
            ldsm_x4(al[0], al[1], al[2], al[3], aLo + kbyte);
#pragma unroll
            for (int p = 0; p < 6; p++) {
                const int nc = wsel * 12 + 2 * p;
                const int w = nc >> 3, nt = nc & 7;
                const uint32_t bbase = bB + (w * 2) * 9216 + nt * 1152 + kbyte;
                uint32_t bh[4], bl[4];
                ldsm_x4(bh[0], bh[1], bh[2], bh[3], bbase);
                ldsm_x4(bl[0], bl[1], bl[2], bl[3], bbase + 9216);
                mma_bf16(acc[2 * p],     ah, bh[0], bh[1]);
                mma_bf16(acc[2 * p],     al, bh[0], bh[1]);
                mma_bf16(acc[2 * p],     ah, bl[0], bl[1]);
                mma_bf16(acc[2 * p + 1], ah, bh[2], bh[3]);
                mma_bf16(acc[2 * p + 1], al, bh[2], bh[3]);
                mma_bf16(acc[2 * p + 1], ah, bl[2], bl[3]);
            }
        }

        if (kb < 15) {
            uint4 H0, L0, H1, L1;
            cvt8(xr, H0, L0); cvt8(xr + 8, H1, L1);
            char* abase = smem_raw + nxt * 36864;
            *(uint4*)(abase + aStoreOff)              = H0;
            *(uint4*)(abase + aStoreOff + 16)         = H1;
            *(uint4*)(abase + 18432 + aStoreOff)      = L0;
            *(uint4*)(abase + 18432 + aStoreOff + 16) = L1;
            if (kb < 14) {
                const float* xs = xrow + (kb + 2) * 64;
                *(float4*)(xr)      = *(const float4*)(xs);
                *(float4*)(xr + 4)  = *(const float4*)(xs + 4);
                *(float4*)(xr + 8)  = *(const float4*)(xs + 8);
                *(float4*)(xr + 12) = *(const float4*)(xs + 12);
            }
        }
        cp_wait_all();
        __syncthreads();
    }

    // ---- epilogue: write split bf16 hi/lo
    __nv_bfloat16* outsH[3] = {g_qh, g_kh, g_vh};
    __nv_bfloat16* outsL[3] = {g_ql, g_kl, g_vl};
    const int rrow = mw * 16 + (L >> 2);
    const int ccol = (L & 3) * 2;
#pragma unroll
    for (int ln = 0; ln < 12; ln++) {
        const int nc = wsel * 12 + ln;
        const int w = nc >> 3, nt = nc & 7;
        const size_t o0 = (size_t)(m0 + rrow) * H_SZ + nt * 8 + ccol;
        const size_t o1 = o0 + 8 * H_SZ;
        uint32_t hi, lo;
        split2(acc[ln][0], acc[ln][1], hi, lo);
        *(uint32_t*)&outsH[w][o0] = hi;
        *(uint32_t*)&outsL[w][o0] = lo;
        split2(acc[ln][2], acc[ln][3], hi, lo);
        *(uint32_t*)&outsH[w][o1] = hi;
        *(uint32_t*)&outsL[w][o1] = lo;
    }
}

// ---------------------------------------------------------------------------
// Kernel 2: causal attention.  512 threads, KV chunk 128, cp.async K/V
// double-buffered, per-warp softmax, P in registers, split-k merge.
// Schedule: 17 bins x 8 batches = 136 CTAs, makespan 16 chunk-units:
//   bin 0 -> {31}, bin 1 -> {30}, bin 2+j -> {29-j, j} (j = 0..14).
// ---------------------------------------------------------------------------
#define AQH 0
#define AQL 9216
#define KBUF(b) (18432 + (b) * 36864)        // hi; lo = +18432
#define VBUF(b) (92160 + (b) * 36864)
#define MRG 18432                            // float [64][68], aliases K bufs
#define SSTAT 165888                         // float2 [64][4]
#define ATTN_SMEM (SSTAT + 2048)             // 167936

__global__ __launch_bounds__(512) void attn_mma_kernel(float* __restrict__ out)
{
    extern __shared__ __align__(128) char smem_raw[];
    const uint32_t sb = smem_u32(smem_raw);
    float* smMrg = (float*)(smem_raw + MRG);
    float2* smSt = (float2*)(smem_raw + SSTAT);

    const int b = blockIdx.y;
    const int bx = blockIdx.x;
    const int t = threadIdx.x;
    const int wid = t >> 5, L = t & 31;
    const int mw = wid & 3, nw = wid >> 2;

    int tiles[2], ntiles;
    if (bx == 0)      { tiles[0] = 31; ntiles = 1; }
    else if (bx == 1) { tiles[0] = 30; ntiles = 1; }
    else              { tiles[0] = 29 - (bx - 2); tiles[1] = bx - 2; ntiles = 2; }

    const int qrow = t >> 3, qseg = t & 7;

    const __nv_bfloat16* qhp = g_qh + (size_t)b * T_SZ * H_SZ;
    const __nv_bfloat16* qlp = g_ql + (size_t)b * T_SZ * H_SZ;
    const __nv_bfloat16* khp = g_kh + (size_t)b * T_SZ * H_SZ;
    const __nv_bfloat16* klp = g_kl + (size_t)b * T_SZ * H_SZ;
    const __nv_bfloat16* vhp = g_vh + (size_t)b * T_SZ * H_SZ;
    const __nv_bfloat16* vlp = g_vl + (size_t)b * T_SZ * H_SZ;

    const uint32_t aQ = AQH + (mw * 16 + (L & 15)) * 144 + (L >> 4) * 16;
    const uint32_t bKoff = ((L & 7) + ((L >> 4) & 1) * 8 + nw * 32) * 144
                         + ((L >> 3) & 1) * 16;
    const uint32_t vJ = (L & 7) + ((L >> 3) & 1) * 8;
    const uint32_t vColB = ((L >> 4) & 1) * 16;

    const int r0 = mw * 16 + (L >> 2);
    const int r1 = r0 + 8;
    const int scol = nw * 32 + (L & 3) * 2;

    for (int pi = 0; pi < ntiles; pi++) {
        const int qb = tiles[pi];
        const int q0 = qb * 64;
        const int nch = (qb + 2) >> 1;
        const int gr0 = q0 + r0, gr1 = q0 + r1;

        __syncthreads();   // protect smem (merge/stat/K/V) from previous pass

        // ---- prologue copies: Q + KV chunk 0 -> buf 0
        cp16(sb + AQH + qrow * 144 + qseg * 16, qhp + (size_t)(q0 + qrow) * 64 + qseg * 8);
        cp16(sb + AQL + qrow * 144 + qseg * 16, qlp + (size_t)(q0 + qrow) * 64 + qseg * 8);
#pragma unroll
        for (int i = 0; i < 2; i++) {
            const int idx = t + i * 512;
            const int row = idx >> 3, seg = idx & 7;
            const uint32_t so = row * 144 + seg * 16;
            const size_t go = (size_t)row * 64 + seg * 8;
            cp16(sb + KBUF(0) + so,         khp + go);
            cp16(sb + KBUF(0) + 18432 + so, klp + go);
            cp16(sb + VBUF(0) + so,         vhp + go);
            cp16(sb + VBUF(0) + 18432 + so, vlp + go);
        }
        cp_commit();

        float m_w0 = -1e30f, m_w1 = -1e30f, l_w0 = 0.0f, l_w1 = 0.0f;
        float acc_o[8][4];
#pragma unroll
        for (int i = 0; i < 8; i++)
#pragma unroll
            for (int j = 0; j < 4; j++) acc_o[i][j] = 0.0f;

        for (int ch = 0; ch < nch; ch++) {
            const int cur = ch & 1;
            cp_wait_all();
            __syncthreads();   // S1: KV cur (+Q on ch 0) visible; prev readers done

            if (ch + 1 < nch) {
                const int nk0 = (ch + 1) * 128;
                const int nxt = cur ^ 1;
#pragma unroll
                for (int i = 0; i < 2; i++) {
                    const int idx = t + i * 512;
                    const int row = idx >> 3, seg = idx & 7;
                    const uint32_t so = row * 144 + seg * 16;
                    const size_t go = (size_t)(nk0 + row) * 64 + seg * 8;
                    cp16(sb + KBUF(nxt) + so,         khp + go);
                    cp16(sb + KBUF(nxt) + 18432 + so, klp + go);
                    cp16(sb + VBUF(nxt) + so,         vhp + go);
                    cp16(sb + VBUF(nxt) + 18432 + so, vlp + go);
                }
                cp_commit();
            }

            // ---- S = Q K^T (3-term), warp tile 16x32
            float s2[4][4];
#pragma unroll
            for (int i = 0; i < 4; i++)
#pragma unroll
                for (int j = 0; j < 4; j++) s2[i][j] = 0.0f;
            const uint32_t bK = sb + KBUF(cur) + bKoff;
#pragma unroll
            for (int ks = 0; ks < 4; ks++) {
                const uint32_t kbyte = ks * 32;
                uint32_t qh[4], ql[4];
                ldsm_x4(qh[0], qh[1], qh[2], qh[3], sb + aQ + kbyte);
                ldsm_x4(ql[0], ql[1], ql[2], ql[3], sb + aQ + 9216 + kbyte);
#pragma unroll
                for (int p = 0; p < 2; p++) {
                    const uint32_t bbase = bK + p * 2304 + kbyte;
                    uint32_t bh[4], bl[4];
                    ldsm_x4(bh[0], bh[1], bh[2], bh[3], bbase);
                    ldsm_x4(bl[0], bl[1], bl[2], bl[3], bbase + 18432);
                    mma_bf16(s2[2 * p],     qh, bh[0], bh[1]);
                    mma_bf16(s2[2 * p],     ql, bh[0], bh[1]);
                    mma_bf16(s2[2 * p],     qh, bl[0], bl[1]);
                    mma_bf16(s2[2 * p + 1], qh, bh[2], bh[3]);
                    mma_bf16(s2[2 * p + 1], ql, bh[2], bh[3]);
                    mma_bf16(s2[2 * p + 1], qh, bl[2], bl[3]);
                }
            }

            // ---- scale + causal mask
            const int k0 = ch * 128;
            const bool last = (ch == nch - 1);
#pragma unroll
            for (int nt = 0; nt < 4; nt++) {
                s2[nt][0] *= 0.03125f; s2[nt][1] *= 0.03125f;
                s2[nt][2] *= 0.03125f; s2[nt][3] *= 0.03125f;
                if (last) {
                    const int gc = k0 + scol + nt * 8;
                    if (gc + 0 > gr0) s2[nt][0] = -1e30f;
                    if (gc + 1 > gr0) s2[nt][1] = -1e30f;
                    if (gc + 0 > gr1) s2[nt][2] = -1e30f;
                    if (gc + 1 > gr1) s2[nt][3] = -1e30f;
                }
            }

            // ---- per-warp online softmax (32-col slice)
            float pm0 = -1e30f, pm1 = -1e30f;
#pragma unroll
            for (int nt = 0; nt < 4; nt++) {
                pm0 = fmaxf(pm0, fmaxf(s2[nt][0], s2[nt][1]));
                pm1 = fmaxf(pm1, fmaxf(s2[nt][2], s2[nt][3]));
            }
            pm0 = qmax(pm0); pm1 = qmax(pm1);
            const float mn0 = fmaxf(m_w0, pm0), mn1 = fmaxf(m_w1, pm1);
            const float alpha0 = __expf(m_w0 - mn0), alpha1 = __expf(m_w1 - mn1);
            float ps0 = 0.0f, ps1 = 0.0f;
#pragma unroll
            for (int nt = 0; nt < 4; nt++) {
                s2[nt][0] = __expf(s2[nt][0] - mn0);
                s2[nt][1] = __expf(s2[nt][1] - mn0);
                s2[nt][2] = __expf(s2[nt][2] - mn1);
                s2[nt][3] = __expf(s2[nt][3] - mn1);
                ps0 += s2[nt][0] + s2[nt][1];
                ps1 += s2[nt][2] + s2[nt][3];
            }
            l_w0 = l_w0 * alpha0 + qsum(ps0);
            l_w1 = l_w1 * alpha1 + qsum(ps1);
            m_w0 = mn0; m_w1 = mn1;

#pragma unroll
            for (int i = 0; i < 8; i++) {
                acc_o[i][0] *= alpha0; acc_o[i][1] *= alpha0;
                acc_o[i][2] *= alpha1; acc_o[i][3] *= alpha1;
            }

            // ---- P (C-frag -> A-frag in regs), O += P V
#pragma unroll
            for (int ks = 0; ks < 2; ks++) {
                uint32_t ph[4], pl[4];
                split2(s2[2 * ks][0],     s2[2 * ks][1],     ph[0], pl[0]);
                split2(s2[2 * ks][2],     s2[2 * ks][3],     ph[1], pl[1]);
                split2(s2[2 * ks + 1][0], s2[2 * ks + 1][1], ph[2], pl[2]);
                split2(s2[2 * ks + 1][2], s2[2 * ks + 1][3], ph[3], pl[3]);
                const uint32_t vrow = sb + VBUF(cur)
                                    + (nw * 32 + ks * 16 + vJ) * 144 + vColB;
#pragma unroll
                for (int vn = 0; vn < 4; vn++) {
                    uint32_t vh[4], vl[4];
                    ldsm_x4_t(vh[0], vh[1], vh[2], vh[3], vrow + vn * 32);
                    ldsm_x4_t(vl[0], vl[1], vl[2], vl[3], vrow + vn * 32 + 18432);
                    mma_bf16(acc_o[2 * vn],     ph, vh[0], vh[1]);
                    mma_bf16(acc_o[2 * vn],     pl, vh[0], vh[1]);
                    mma_bf16(acc_o[2 * vn],     ph, vl[0], vl[1]);
                    mma_bf16(acc_o[2 * vn + 1], ph, vh[2], vh[3]);
                    mma_bf16(acc_o[2 * vn + 1], pl, vh[2], vh[3]);
                    mma_bf16(acc_o[2 * vn + 1], ph, vl[2], vl[3]);
                }
            }
        }

        // ---- split-k merge across the 4 nw groups
        if ((L & 3) == 0) {
            smSt[r0 * 4 + nw] = make_float2(m_w0, l_w0);
            smSt[r1 * 4 + nw] = make_float2(m_w1, l_w1);
        }
        __syncthreads();
        float f0, f1;
        {
            float2 e0[4], e1[4];
#pragma unroll
            for (int i = 0; i < 4; i++) { e0[i] = smSt[r0 * 4 + i]; e1[i] = smSt[r1 * 4 + i]; }
            float M0 = e0[0].x, M1 = e1[0].x;
#pragma unroll
            for (int i = 1; i < 4; i++) { M0 = fmaxf(M0, e0[i].x); M1 = fmaxf(M1, e1[i].x); }
            float Lt0 = 0.0f, Lt1 = 0.0f;
#pragma unroll
            for (int i = 0; i < 4; i++) {
                Lt0 += e0[i].y * __expf(e0[i].x - M0);
                Lt1 += e1[i].y * __expf(e1[i].x - M1);
            }
            f0 = __expf(m_w0 - M0) / Lt0;
            f1 = __expf(m_w1 - M1) / Lt1;
        }
#pragma unroll
        for (int i = 0; i < 8; i++) {
            acc_o[i][0] *= f0; acc_o[i][1] *= f0;
            acc_o[i][2] *= f1; acc_o[i][3] *= f1;
        }

        const int mc = (L & 3) * 2;
        if (nw == 0) {
#pragma unroll
            for (int vn = 0; vn < 8; vn++) {
                *(float2*)&smMrg[r0 * 68 + vn * 8 + mc] = make_float2(acc_o[vn][0], acc_o[vn][1]);
                *(float2*)&smMrg[r1 * 68 + vn * 8 + mc] = make_float2(acc_o[vn][2], acc_o[vn][3]);
            }
        }
        __syncthreads();
        if (nw == 1) {
#pragma unroll
            for (int vn = 0; vn < 8; vn++) {
                float2 a = *(float2*)&smMrg[r0 * 68 + vn * 8 + mc];
                *(float2*)&smMrg[r0 * 68 + vn * 8 + mc] = make_float2(a.x + acc_o[vn][0], a.y + acc_o[vn][1]);
                float2 c = *(float2*)&smMrg[r1 * 68 + vn * 8 + mc];
                *(float2*)&smMrg[r1 * 68 + vn * 8 + mc] = make_float2(c.x + acc_o[vn][2], c.y + acc_o[vn][3]);
            }
        }
        __syncthreads();
        if (nw == 2) {
#pragma unroll
            for (int vn = 0; vn < 8; vn++) {
                float2 a = *(float2*)&smMrg[r0 * 68 + vn * 8 + mc];
                *(float2*)&smMrg[r0 * 68 + vn * 8 + mc] = make_float2(a.x + acc_o[vn][0], a.y + acc_o[vn][1]);
                float2 c = *(float2*)&smMrg[r1 * 68 + vn * 8 + mc];
                *(float2*)&smMrg[r1 * 68 + vn * 8 + mc] = make_float2(c.x + acc_o[vn][2], c.y + acc_o[vn][3]);
            }
        }
        __syncthreads();
        if (nw == 3) {
#pragma unroll
            for (int vn = 0; vn < 8; vn++) {
                float2 a = *(float2*)&smMrg[r0 * 68 + vn * 8 + mc];
                float2 c = *(float2*)&smMrg[r1 * 68 + vn * 8 + mc];
                *(float2*)(out + (size_t)(b * T_SZ + gr0) * H_SZ + vn * 8 + mc)
                    = make_float2(a.x + acc_o[vn][0], a.y + acc_o[vn][1]);
                *(float2*)(out + (size_t)(b * T_SZ + gr1) * H_SZ + vn * 8 + mc)
                    = make_float2(c.x + acc_o[vn][2], c.y + acc_o[vn][3]);
            }
        }
    }
}

// ---------------------------------------------------------------------------
extern "C" void kernel_launch(void* const* d_in, const int* in_sizes, int n_in,
                              void* d_out, int out_size)
{
    const float* x  = (const float*)d_in[0];
    const float* Wq = (const float*)d_in[1];
    const float* Wk = (const float*)d_in[2];
    const float* Wv = (const float*)d_in[3];
    float* out = (float*)d_out;

    cudaFuncSetAttribute(qkv_mma_kernel, cudaFuncAttributeMaxDynamicSharedMemorySize,
                         QKV_SMEM);
    cudaFuncSetAttribute(attn_mma_kernel, cudaFuncAttributeMaxDynamicSharedMemorySize,
                         ATTN_SMEM);

    wsplit_kernel<<<dim3(16, 3), 256>>>(Wq, Wk, Wv);
    qkv_mma_kernel<<<MROWS / 128, 512, QKV_SMEM>>>(x);
    attn_mma_kernel<<<dim3(17, B_SZ), 512, ATTN_SMEM>>>(out);
}